// round 15
// baseline (speedup 1.0000x reference)
#include <cuda_runtime.h>
#include <cuda_fp16.h>
#include <math.h>
#include <stdint.h>

#define D_MODEL 1024
#define T_LEN   2048
#define BATCH   2
#define N_HEADS 16
#define D_HEAD  64
#define BT      (BATCH * T_LEN)
#define W_ELEMS (D_MODEL * D_MODEL)

#define SPLIT_UP   2048.0f
#define SPLIT_UP2  4194304.0f
#define SPLIT_DN   4.8828125e-4f

// ---------------- static scratch ----------------
__device__ __half g_Tw[4][W_ELEMS];
__device__ __half g_X1[BT * D_MODEL], g_X2[BT * D_MODEL], g_X3[BT * D_MODEL];
__device__ __half g_Q1[BT * D_MODEL], g_Q2[BT * D_MODEL], g_Q3[BT * D_MODEL];
__device__ __half g_K1[BT * D_MODEL], g_K2[BT * D_MODEL], g_K3[BT * D_MODEL];
__device__ float  g_V[BT * D_MODEL];
__device__ __half g_Vt1[BT * D_MODEL], g_Vt2[BT * D_MODEL], g_Vt3[BT * D_MODEL];
__device__ __half g_O1[BT * D_MODEL], g_O2[BT * D_MODEL], g_O3[BT * D_MODEL];
__device__ float  g_Y[BT * D_MODEL];
__device__ float  g_S[(size_t)BATCH * N_HEADS * T_LEN * T_LEN];   // 512 MB
__device__ unsigned g_rmax[BATCH * N_HEADS * T_LEN];
__device__ unsigned g_ymax;
__device__ double g_red[4][1024], g_red2a[4][1024], g_red2b[4][1024];
__device__ float  g_delta[4], g_alphaf[4];

// ---------------- helpers ----------------
__device__ __forceinline__ uint32_t smem_u32(const void* p) {
    uint32_t a;
    asm("{ .reg .u64 t; cvta.to.shared.u64 t, %1; cvt.u32.u64 %0, t; }" : "=r"(a) : "l"(p));
    return a;
}
__device__ __forceinline__ void ldsm4(uint32_t (&r)[4], uint32_t addr) {
    asm volatile("ldmatrix.sync.aligned.m8n8.x4.shared.b16 {%0,%1,%2,%3}, [%4];"
                 : "=r"(r[0]), "=r"(r[1]), "=r"(r[2]), "=r"(r[3]) : "r"(addr));
}
__device__ __forceinline__ void mma16816(float (&d)[4], const uint32_t (&a)[4],
                                         uint32_t b0, uint32_t b1) {
    asm volatile("mma.sync.aligned.m16n8k16.row.col.f32.f16.f16.f32 "
                 "{%0,%1,%2,%3}, {%4,%5,%6,%7}, {%8,%9}, {%0,%1,%2,%3};"
                 : "+f"(d[0]), "+f"(d[1]), "+f"(d[2]), "+f"(d[3])
                 : "r"(a[0]), "r"(a[1]), "r"(a[2]), "r"(a[3]), "r"(b0), "r"(b1));
}
__device__ __forceinline__ unsigned fenc(float f) {
    unsigned b = __float_as_uint(f);
    return (b & 0x80000000u) ? ~b : (b | 0x80000000u);
}
__device__ __forceinline__ float fdec(unsigned u) {
    unsigned b = (u & 0x80000000u) ? (u & 0x7FFFFFFFu) : ~u;
    return __uint_as_float(b);
}
__device__ __forceinline__ void split3s(float y, __half& p1, __half& p2, __half& p3) {
    p1 = __float2half_rn(y);
    float r = y - __half2float(p1);
    p2 = __float2half_rn(r * SPLIT_UP);
    float r2 = r - __half2float(p2) * SPLIT_DN;
    p3 = __float2half_rn(r2 * SPLIT_UP2);
}
__device__ __forceinline__ uint32_t packh2(__half a, __half b) {
    __half2 h = __halves2half2(a, b);
    return *(uint32_t*)&h;
}

// ---------------- weight stats (byte-identical arithmetic) ----------------
__device__ __forceinline__ const float* pick_w(const float* W0, const float* W1,
                                               const float* W2, const float* W3, int y) {
    return y == 0 ? W0 : (y == 1 ? W1 : (y == 2 ? W2 : W3));
}

__global__ void k_wabs(const float* __restrict__ W0, const float* __restrict__ W1,
                       const float* __restrict__ W2, const float* __restrict__ W3) {
    if (blockIdx.y == 0) {
        int gi = blockIdx.x * 256 + threadIdx.x;
        if (gi < BATCH * N_HEADS * T_LEN) g_rmax[gi] = 0u;
        if (gi == 0) g_ymax = 0u;
    }
    const float* W = pick_w(W0, W1, W2, W3, blockIdx.y);
    __shared__ double sm[256];
    int base = blockIdx.x * 1024;
    double s = 0.0;
    for (int i = threadIdx.x; i < 1024; i += 256) s += (double)fabsf(W[base + i]);
    sm[threadIdx.x] = s; __syncthreads();
    for (int st = 128; st > 0; st >>= 1) {
        if (threadIdx.x < st) sm[threadIdx.x] += sm[threadIdx.x + st];
        __syncthreads();
    }
    if (threadIdx.x == 0) g_red[blockIdx.y][blockIdx.x] = sm[0];
}
__global__ void k_wmask(const float* __restrict__ W0, const float* __restrict__ W1,
                        const float* __restrict__ W2, const float* __restrict__ W3) {
    int y = blockIdx.y;
    const float* W = pick_w(W0, W1, W2, W3, y);
    __shared__ double sa[256], sb[256];
    double s = 0.0;
    for (int i = threadIdx.x; i < 1024; i += 256) s += g_red[y][i];
    sa[threadIdx.x] = s; __syncthreads();
    for (int st = 128; st > 0; st >>= 1) {
        if (threadIdx.x < st) sa[threadIdx.x] += sa[threadIdx.x + st];
        __syncthreads();
    }
    float delta = (float)(0.05 * (sa[0] / (double)W_ELEMS));
    if (blockIdx.x == 0 && threadIdx.x == 0) g_delta[y] = delta;
    __syncthreads();
    int base = blockIdx.x * 1024;
    double s1 = 0.0, s2 = 0.0;
    for (int i = threadIdx.x; i < 1024; i += 256) {
        float a = fabsf(W[base + i]);
        if (a > delta) { s1 += (double)a; s2 += 1.0; }
    }
    sa[threadIdx.x] = s1; sb[threadIdx.x] = s2; __syncthreads();
    for (int st = 128; st > 0; st >>= 1) {
        if (threadIdx.x < st) { sa[threadIdx.x] += sa[threadIdx.x + st]; sb[threadIdx.x] += sb[threadIdx.x + st]; }
        __syncthreads();
    }
    if (threadIdx.x == 0) { g_red2a[y][blockIdx.x] = sa[0]; g_red2b[y][blockIdx.x] = sb[0]; }
}
__global__ void k_walpha() {
    int y = blockIdx.x;
    __shared__ double sa[1024], sb[1024];
    sa[threadIdx.x] = g_red2a[y][threadIdx.x];
    sb[threadIdx.x] = g_red2b[y][threadIdx.x];
    __syncthreads();
    for (int st = 512; st > 0; st >>= 1) {
        if (threadIdx.x < st) { sa[threadIdx.x] += sa[threadIdx.x + st]; sb[threadIdx.x] += sb[threadIdx.x + st]; }
        __syncthreads();
    }
    if (threadIdx.x == 0) g_alphaf[y] = (float)(sa[0] / fmax(sb[0], 1.0));
}
__global__ void k_wtern(const float* __restrict__ W0, const float* __restrict__ W1,
                        const float* __restrict__ W2, const float* __restrict__ W3) {
    int y = blockIdx.y;
    const float* W = pick_w(W0, W1, W2, W3, y);
    float delta = g_delta[y];
    int i0 = (blockIdx.x * 1024 + threadIdx.x) * 8;
    float4 wa = *(const float4*)(W + i0);
    float4 wb = *(const float4*)(W + i0 + 4);
    float wv[8] = {wa.x, wa.y, wa.z, wa.w, wb.x, wb.y, wb.z, wb.w};
    __half h[8];
#pragma unroll
    for (int q = 0; q < 8; q++) {
        float w = wv[q];
        float t = (fabsf(w) > delta) ? ((w > 0.0f) ? 1.0f : -1.0f) : 0.0f;
        h[q] = __float2half_rn(t);
    }
    *(uint4*)(g_Tw[y] + i0) = *(uint4*)&h[0];
}
__global__ void k_split3(const float* __restrict__ X) {
    int i0 = (blockIdx.x * 1024 + threadIdx.x) * 8;
    float4 xa = *(const float4*)(X + i0);
    float4 xb = *(const float4*)(X + i0 + 4);
    float xv[8] = {xa.x, xa.y, xa.z, xa.w, xb.x, xb.y, xb.z, xb.w};
    __half h1[8], h2[8], h3[8];
#pragma unroll
    for (int q = 0; q < 8; q++) split3s(xv[q], h1[q], h2[q], h3[q]);
    *(uint4*)(g_X1 + i0) = *(uint4*)&h1[0];
    *(uint4*)(g_X2 + i0) = *(uint4*)&h2[0];
    *(uint4*)(g_X3 + i0) = *(uint4*)&h3[0];
}

// ---------------- tile staging ----------------
struct TileRegs { uint4 v[4]; };
__device__ __forceinline__ void tile_ldg(TileRegs& r, const __half* __restrict__ g,
                                         int row0, int col0, int lda) {
    int tid = threadIdx.x;
#pragma unroll
    for (int i = 0; i < 4; i++) {
        int idx = tid + i * 256;
        int row = idx >> 3, c = idx & 7;
        r.v[i] = *(const uint4*)(g + (size_t)(row0 + row) * lda + col0 + c * 8);
    }
}
__device__ __forceinline__ void tile_sts(__half* s, const TileRegs& r) {
    int tid = threadIdx.x;
#pragma unroll
    for (int i = 0; i < 4; i++) {
        int idx = tid + i * 256;
        int row = idx >> 3, c = idx & 7;
        int cs = c ^ (row & 7);
        *(uint4*)((char*)s + row * 128 + cs * 16) = r.v[i];
    }
}
__device__ __forceinline__ void load_tile3(__half* s0, __half* s1, __half* s2,
                                           const __half* __restrict__ g0,
                                           const __half* __restrict__ g1,
                                           const __half* __restrict__ g2,
                                           int row0, int col0, int lda) {
    TileRegs r0, r1, r2;
    tile_ldg(r0, g0, row0, col0, lda);
    tile_ldg(r1, g1, row0, col0, lda);
    tile_ldg(r2, g2, row0, col0, lda);
    tile_sts(s0, r0);
    tile_sts(s1, r1);
    tile_sts(s2, r2);
}

// 128x128 HMMA stage
__device__ __forceinline__ void hgemm_core(uint32_t aB, uint32_t bB, int wm, int wn,
                                           int lane, float (&acc)[4][4][4]) {
#pragma unroll
    for (int kf = 0; kf < 4; kf++) {
        uint32_t a[4][4];
#pragma unroll
        for (int i = 0; i < 4; i++) {
            int row = wm * 64 + i * 16 + (lane & 15);
            int ch = (kf * 2 + (lane >> 4)) ^ (row & 7);
            ldsm4(a[i], aB + (uint32_t)(row * 8 + ch) * 16);
        }
        uint32_t b[4][2];
#pragma unroll
        for (int jp = 0; jp < 2; jp++) {
            int nrow = wn * 32 + jp * 16 + (lane & 7) + ((lane >> 4) << 3);
            int ch = (kf * 2 + ((lane >> 3) & 1)) ^ (nrow & 7);
            uint32_t t[4];
            ldsm4(t, bB + (uint32_t)(nrow * 8 + ch) * 16);
            b[jp * 2][0] = t[0]; b[jp * 2][1] = t[1];
            b[jp * 2 + 1][0] = t[2]; b[jp * 2 + 1][1] = t[3];
        }
#pragma unroll
        for (int i = 0; i < 4; i++)
#pragma unroll
            for (int j = 0; j < 4; j++)
                mma16816(acc[i][j], a[i], b[j][0], b[j][1]);
    }
}
__device__ __forceinline__ void acc_scale(float (&acc)[4][4][4], float s) {
#pragma unroll
    for (int i = 0; i < 4; i++)
#pragma unroll
        for (int j = 0; j < 4; j++)
#pragma unroll
            for (int q = 0; q < 4; q++) acc[i][j][q] *= s;
}
// 128x64 HMMA stage (PV)
__device__ __forceinline__ void hgemm64(uint32_t aB, uint32_t bB, int wm, int wn,
                                        int lane, float (&acc)[2][4][4]) {
#pragma unroll
    for (int kf = 0; kf < 4; kf++) {
        uint32_t a[2][4];
#pragma unroll
        for (int i = 0; i < 2; i++) {
            int row = wm * 32 + i * 16 + (lane & 15);
            int ch = (kf * 2 + (lane >> 4)) ^ (row & 7);
            ldsm4(a[i], aB + (uint32_t)(row * 8 + ch) * 16);
        }
        uint32_t b[4][2];
#pragma unroll
        for (int jp = 0; jp < 2; jp++) {
            int nrow = wn * 32 + jp * 16 + (lane & 7) + ((lane >> 4) << 3);
            int ch = (kf * 2 + ((lane >> 3) & 1)) ^ (nrow & 7);
            uint32_t t[4];
            ldsm4(t, bB + (uint32_t)(nrow * 8 + ch) * 16);
            b[jp * 2][0] = t[0]; b[jp * 2][1] = t[1];
            b[jp * 2 + 1][0] = t[2]; b[jp * 2 + 1][1] = t[3];
        }
#pragma unroll
        for (int i = 0; i < 2; i++)
#pragma unroll
            for (int j = 0; j < 4; j++)
                mma16816(acc[i][j], a[i], b[j][0], b[j][1]);
    }
}

// ---------------- projection body: double-buffered, one sync per stage ----------------
__device__ __forceinline__ void hproj_body(
        const __half* __restrict__ A0, const __half* __restrict__ A1,
        const __half* __restrict__ A2, const __half* __restrict__ Bw, int widx,
        const float* __restrict__ bias, float* __restrict__ outF,
        __half* __restrict__ O1, __half* __restrict__ O2, __half* __restrict__ O3,
        int mode, int do_absmax, char* smp) {
    char* sAb[2] = {smp, smp + 32768};
    char* sBb[2] = {smp + 16384, smp + 49152};

    int tid = threadIdx.x, lane = tid & 31, w = tid >> 5, wm = w >> 2, wn = w & 3;
    int m0 = blockIdx.x * 128, n0 = blockIdx.y * 128;
    float acc[4][4][4];
#pragma unroll
    for (int i = 0; i < 4; i++)
#pragma unroll
        for (int j = 0; j < 4; j++)
#pragma unroll
            for (int q = 0; q < 4; q++) acc[i][j][q] = 0.0f;

    const __half* As3[3] = {A2, A1, A0};
    TileRegs ra, rb;
    // prologue: stage 0 into buf0, prefetch stage 1 into regs
    tile_ldg(ra, As3[0], m0, 0, D_MODEL);
    tile_ldg(rb, Bw, n0, 0, D_MODEL);
    tile_sts((__half*)sAb[0], ra);
    tile_sts((__half*)sBb[0], rb);
    tile_ldg(ra, As3[0], m0, 64, D_MODEL);
    tile_ldg(rb, Bw, n0, 64, D_MODEL);
    __syncthreads();

    for (int st = 0; st < 48; st++) {
        int buf = st & 1;
        if (st < 47) {                   // STS stage st+1 into the other buffer
            tile_sts((__half*)sAb[buf ^ 1], ra);
            tile_sts((__half*)sBb[buf ^ 1], rb);
        }
        if (st < 46) {                   // prefetch stage st+2
            int nst = st + 2;
            tile_ldg(ra, As3[nst >> 4], m0, (nst & 15) * 64, D_MODEL);
            tile_ldg(rb, Bw, n0, (nst & 15) * 64, D_MODEL);
        }
        hgemm_core(smem_u32(sAb[buf]), smem_u32(sBb[buf]), wm, wn, lane, acc);
        if (st == 15 || st == 31) acc_scale(acc, SPLIT_DN);
        __syncthreads();
    }

    float alpha = g_alphaf[widx];
    int gid = lane >> 2, tid2 = lane & 3;
    float lmax = 0.0f;
#pragma unroll
    for (int i = 0; i < 4; i++) {
#pragma unroll
        for (int j = 0; j < 4; j++) {
            int row = m0 + wm * 64 + i * 16 + gid;
            int col = n0 + wn * 32 + j * 8 + tid2 * 2;
            float b0 = bias[col], b1 = bias[col + 1];
            float y00 = acc[i][j][0] * alpha + b0, y01 = acc[i][j][1] * alpha + b1;
            float y10 = acc[i][j][2] * alpha + b0, y11 = acc[i][j][3] * alpha + b1;
            if (mode == 0) {
                *(float2*)(outF + (size_t)row * D_MODEL + col) = make_float2(y00, y01);
                *(float2*)(outF + (size_t)(row + 8) * D_MODEL + col) = make_float2(y10, y11);
                if (do_absmax)
                    lmax = fmaxf(lmax, fmaxf(fmaxf(fabsf(y00), fabsf(y01)),
                                             fmaxf(fabsf(y10), fabsf(y11))));
            } else {
                __half u1, u2, u3, v1, v2, v3;
                size_t r0 = (size_t)row * D_MODEL + col;
                size_t r1 = (size_t)(row + 8) * D_MODEL + col;
                split3s(y00, u1, u2, u3); split3s(y01, v1, v2, v3);
                *(uint32_t*)(O1 + r0) = packh2(u1, v1);
                *(uint32_t*)(O2 + r0) = packh2(u2, v2);
                *(uint32_t*)(O3 + r0) = packh2(u3, v3);
                split3s(y10, u1, u2, u3); split3s(y11, v1, v2, v3);
                *(uint32_t*)(O1 + r1) = packh2(u1, v1);
                *(uint32_t*)(O2 + r1) = packh2(u2, v2);
                *(uint32_t*)(O3 + r1) = packh2(u3, v3);
            }
        }
    }
    if (mode == 0 && do_absmax) {
#pragma unroll
        for (int off = 16; off > 0; off >>= 1)
            lmax = fmaxf(lmax, __shfl_xor_sync(0xFFFFFFFF, lmax, off));
        if (lane == 0) atomicMax(&g_ymax, __float_as_uint(lmax));
    }
}

__global__ void __launch_bounds__(256)
k_hproj_qkv(const __half* __restrict__ x1, const __half* __restrict__ x2,
            const __half* __restrict__ x3, const __half* __restrict__ tw,
            const float* __restrict__ bq, const float* __restrict__ bk,
            const float* __restrict__ bv, float* __restrict__ vout,
            __half* __restrict__ q1, __half* __restrict__ q2, __half* __restrict__ q3,
            __half* __restrict__ kk1, __half* __restrict__ kk2, __half* __restrict__ kk3) {
    extern __shared__ __align__(16) char smp[];
    int z = blockIdx.z;
    const __half* Bw = tw + (size_t)z * W_ELEMS;
    const float* bias = (z == 0) ? bq : (z == 1 ? bk : bv);
    if (z == 2)
        hproj_body(x1, x2, x3, Bw, 2, bias, vout, nullptr, nullptr, nullptr, 0, 0, smp);
    else if (z == 0)
        hproj_body(x1, x2, x3, Bw, 0, bias, nullptr, q1, q2, q3, 1, 0, smp);
    else
        hproj_body(x1, x2, x3, Bw, 1, bias, nullptr, kk1, kk2, kk3, 1, 0, smp);
}

__global__ void __launch_bounds__(256)
k_hproj(const __half* __restrict__ A0, const __half* __restrict__ A1,
        const __half* __restrict__ A2, const __half* __restrict__ Bw, int widx,
        const float* __restrict__ bias, float* __restrict__ outF) {
    extern __shared__ __align__(16) char smp[];
    hproj_body(A0, A1, A2, Bw, widx, bias, outF, nullptr, nullptr, nullptr, 0, 1, smp);
}

// ---------------- V transpose + split ----------------
__global__ void __launch_bounds__(256)
k_vsplitT() {
    __shared__ float sT[64][65];
    int t0 = blockIdx.x * 64, d0 = blockIdx.y * 64, b = blockIdx.z;
    int tid = threadIdx.x;
    const float* V = g_V + ((size_t)b * T_LEN) * D_MODEL;
#pragma unroll
    for (int i = 0; i < 4; i++) {
        int idx4 = tid + i * 256;
        int tok = idx4 >> 4, c4 = idx4 & 15;
        float4 v = *(const float4*)(V + (size_t)(t0 + tok) * D_MODEL + d0 + c4 * 4);
        sT[tok][c4 * 4 + 0] = v.x;
        sT[tok][c4 * 4 + 1] = v.y;
        sT[tok][c4 * 4 + 2] = v.z;
        sT[tok][c4 * 4 + 3] = v.w;
    }
    __syncthreads();
    int d = tid >> 2, chunk = tid & 3;
    __half h1[16], h2[16], h3[16];
#pragma unroll
    for (int j = 0; j < 16; j++)
        split3s(sT[chunk * 16 + j][d], h1[j], h2[j], h3[j]);
    size_t base = ((size_t)b * D_MODEL + d0 + d) * T_LEN + t0 + chunk * 16;
    *(uint4*)(g_Vt1 + base) = *(uint4*)&h1[0];
    *(uint4*)(g_Vt1 + base + 8) = *(uint4*)&h1[8];
    *(uint4*)(g_Vt2 + base) = *(uint4*)&h2[0];
    *(uint4*)(g_Vt2 + base + 8) = *(uint4*)&h2[8];
    *(uint4*)(g_Vt3 + base) = *(uint4*)&h3[0];
    *(uint4*)(g_Vt3 + base + 8) = *(uint4*)&h3[8];
}

// ---------------- S = (QK^T)/8 + row max ----------------
__global__ void __launch_bounds__(256)
k_hs() {
    extern __shared__ __align__(16) __half sms[];
    __half* sQ[3] = {sms, sms + 8192, sms + 16384};
    __half* sK[3] = {sms + 24576, sms + 32768, sms + 40960};

    int tid = threadIdx.x, lane = tid & 31, w = tid >> 5, wm = w >> 2, wn = w & 3;
    int z = blockIdx.z, b = z >> 4, h = z & 15;
    int arow0 = b * T_LEN + blockIdx.x * 128;
    int brow0 = b * T_LEN + blockIdx.y * 128;
    int col0 = h * 64;
    float acc[4][4][4];
#pragma unroll
    for (int i = 0; i < 4; i++)
#pragma unroll
        for (int j = 0; j < 4; j++)
#pragma unroll
            for (int q = 0; q < 4; q++) acc[i][j][q] = 0.0f;

    load_tile3(sQ[0], sQ[1], sQ[2], g_Q1, g_Q2, g_Q3, arow0, col0, D_MODEL);
    load_tile3(sK[0], sK[1], sK[2], g_K1, g_K2, g_K3, brow0, col0, D_MODEL);
    __syncthreads();

    uint32_t qB[3] = {smem_u32(sQ[0]), smem_u32(sQ[1]), smem_u32(sQ[2])};
    uint32_t kB[3] = {smem_u32(sK[0]), smem_u32(sK[1]), smem_u32(sK[2])};
    hgemm_core(qB[1], kB[1], wm, wn, lane, acc);
    hgemm_core(qB[0], kB[2], wm, wn, lane, acc);
    hgemm_core(qB[2], kB[0], wm, wn, lane, acc);
    acc_scale(acc, SPLIT_DN);
    hgemm_core(qB[0], kB[1], wm, wn, lane, acc);
    hgemm_core(qB[1], kB[0], wm, wn, lane, acc);
    acc_scale(acc, SPLIT_DN);
    hgemm_core(qB[0], kB[0], wm, wn, lane, acc);

    int gid = lane >> 2, tid2 = lane & 3;
    size_t zrow = (size_t)z * T_LEN;
#pragma unroll
    for (int i = 0; i < 4; i++) {
        int rl0 = blockIdx.x * 128 + wm * 64 + i * 16 + gid;
        float m0v = -INFINITY, m1v = -INFINITY;
#pragma unroll
        for (int j = 0; j < 4; j++) {
            int col = blockIdx.y * 128 + wn * 32 + j * 8 + tid2 * 2;
            float y00 = acc[i][j][0] * 0.125f, y01 = acc[i][j][1] * 0.125f;
            float y10 = acc[i][j][2] * 0.125f, y11 = acc[i][j][3] * 0.125f;
            *(float2*)(g_S + (zrow + rl0) * T_LEN + col) = make_float2(y00, y01);
            *(float2*)(g_S + (zrow + rl0 + 8) * T_LEN + col) = make_float2(y10, y11);
            m0v = fmaxf(m0v, fmaxf(y00, y01));
            m1v = fmaxf(m1v, fmaxf(y10, y11));
        }
        atomicMax(&g_rmax[zrow + rl0], fenc(m0v));
        atomicMax(&g_rmax[zrow + rl0 + 8], fenc(m1v));
    }
}

// ---- HMMA softmax+PV: double-buffered, exp||MMA ----
__global__ void __launch_bounds__(256)
k_pvh() {
    extern __shared__ __align__(16) char smv[];
    __shared__ float m_s[128];
    __shared__ float rs2[256];
    __shared__ float rsum_s[128];

    int tid = threadIdx.x, lane = tid & 31, w = tid >> 5;
    int wm = w >> 1, wn = w & 1;
    int z = blockIdx.y, b = z >> 4, h = z & 15;
    int rowBase = blockIdx.x * 128;
    const float* Sp = g_S + ((size_t)z * T_LEN + rowBase) * T_LEN;
    size_t vbase = (size_t)b * D_MODEL + h * 64;

    if (tid < 128) m_s[tid] = fdec(g_rmax[(size_t)z * T_LEN + rowBase + tid]);
    __syncthreads();

    float acc[2][4][4], compA[2][4][4];
#pragma unroll
    for (int i = 0; i < 2; i++)
#pragma unroll
        for (int j = 0; j < 4; j++)
#pragma unroll
            for (int q = 0; q < 4; q++) { acc[i][j][q] = 0.0f; compA[i][j][q] = 0.0f; }
    float rs = 0.0f, rcomp = 0.0f;

    int prow = tid >> 1;
    int pcb = (tid & 1) * 32;
    float pm = m_s[prow];

    int vrow0 = tid >> 3, vc0 = tid & 7;
    int vrow1 = (tid + 256) >> 3, vc1 = (tid + 256) & 7;
    uint32_t voff0 = (uint32_t)vrow0 * 128 + (uint32_t)((vc0 ^ (vrow0 & 7)) * 16);
    uint32_t voff1 = (uint32_t)vrow1 * 128 + (uint32_t)((vc1 ^ (vrow1 & 7)) * 16);

    float4 sv[8];
    uint4 vv[2][3];

#define LD_STAGE(kk) do { \
    int _k0 = (kk) * 64; \
    _Pragma("unroll") \
    for (int cc = 0; cc < 4; cc++) { \
        int colb = pcb + cc * 8; \
        sv[cc * 2]     = *(const float4*)(Sp + (size_t)prow * T_LEN + _k0 + colb); \
        sv[cc * 2 + 1] = *(const float4*)(Sp + (size_t)prow * T_LEN + _k0 + colb + 4); \
    } \
    { size_t _s0 = (vbase + vrow0) * T_LEN + _k0 + vc0 * 8; \
      vv[0][0] = *(const uint4*)(g_Vt1 + _s0); \
      vv[0][1] = *(const uint4*)(g_Vt2 + _s0); \
      vv[0][2] = *(const uint4*)(g_Vt3 + _s0); } \
    { size_t _s1 = (vbase + vrow1) * T_LEN + _k0 + vc1 * 8; \
      vv[1][0] = *(const uint4*)(g_Vt1 + _s1); \
      vv[1][1] = *(const uint4*)(g_Vt2 + _s1); \
      vv[1][2] = *(const uint4*)(g_Vt3 + _s1); } \
} while (0)

#define EXP_STS(bufb) do { \
    char* _P0 = smv + (bufb) * 73728; \
    char* _P1 = _P0 + 16384; \
    char* _P2 = _P0 + 32768; \
    char* _V0 = _P0 + 49152; \
    char* _V1 = _P0 + 57344; \
    char* _V2 = _P0 + 65536; \
    float csum = 0.0f; \
    _Pragma("unroll") \
    for (int cc = 0; cc < 4; cc++) { \
        int colb = pcb + cc * 8; \
        float4 v0 = sv[cc * 2], v1 = sv[cc * 2 + 1]; \
        float e[8] = {expf(v0.x - pm), expf(v0.y - pm), expf(v0.z - pm), expf(v0.w - pm), \
                      expf(v1.x - pm), expf(v1.y - pm), expf(v1.z - pm), expf(v1.w - pm)}; \
        _Pragma("unroll") \
        for (int q = 0; q < 8; q++) csum += e[q]; \
        __half h1[8], h2[8], h3[8]; \
        _Pragma("unroll") \
        for (int q = 0; q < 8; q++) split3s(e[q], h1[q], h2[q], h3[q]); \
        int c16 = colb >> 3; \
        int cs = c16 ^ (prow & 7); \
        uint32_t off = (uint32_t)prow * 128 + cs * 16; \
        *(uint4*)(_P0 + off) = *(uint4*)&h1[0]; \
        *(uint4*)(_P1 + off) = *(uint4*)&h2[0]; \
        *(uint4*)(_P2 + off) = *(uint4*)&h3[0]; \
    } \
    { float yv = csum - rcomp; float t = rs + yv; rcomp = (t - rs) - yv; rs = t; } \
    *(uint4*)(_V0 + voff0) = vv[0][0]; \
    *(uint4*)(_V1 + voff0) = vv[0][1]; \
    *(uint4*)(_V2 + voff0) = vv[0][2]; \
    *(uint4*)(_V0 + voff1) = vv[1][0]; \
    *(uint4*)(_V1 + voff1) = vv[1][1]; \
    *(uint4*)(_V2 + voff1) = vv[1][2]; \
} while (0)

    LD_STAGE(0);
    EXP_STS(0);
    LD_STAGE(1);
    __syncthreads();

    for (int k = 0; k < 32; k++) {
        int kb = k & 1;
        uint32_t base = smem_u32(smv + kb * 73728);
        uint32_t aP0 = base, aP1 = base + 16384, aP2 = base + 32768;
        uint32_t bV0 = base + 49152, bV1 = base + 57344, bV2 = base + 65536;

        if (k < 31) {
            EXP_STS((k + 1) & 1);
            if (k < 30) LD_STAGE(k + 2);
        }

        float cacc[2][4][4];
#pragma unroll
        for (int i = 0; i < 2; i++)
#pragma unroll
            for (int j = 0; j < 4; j++)
#pragma unroll
                for (int q = 0; q < 4; q++) cacc[i][j][q] = 0.0f;
        hgemm64(aP0, bV2, wm, wn, lane, cacc);
        hgemm64(aP1, bV1, wm, wn, lane, cacc);
        hgemm64(aP2, bV0, wm, wn, lane, cacc);
#pragma unroll
        for (int i = 0; i < 2; i++)
#pragma unroll
            for (int j = 0; j < 4; j++)
#pragma unroll
                for (int q = 0; q < 4; q++) cacc[i][j][q] *= SPLIT_DN;
        hgemm64(aP0, bV1, wm, wn, lane, cacc);
        hgemm64(aP1, bV0, wm, wn, lane, cacc);
#pragma unroll
        for (int i = 0; i < 2; i++)
#pragma unroll
            for (int j = 0; j < 4; j++)
#pragma unroll
                for (int q = 0; q < 4; q++) cacc[i][j][q] *= SPLIT_DN;
        hgemm64(aP0, bV0, wm, wn, lane, cacc);
#pragma unroll
        for (int i = 0; i < 2; i++)
#pragma unroll
            for (int j = 0; j < 4; j++)
#pragma unroll
                for (int q = 0; q < 4; q++) {
                    float ya = cacc[i][j][q] - compA[i][j][q];
                    float ta = acc[i][j][q] + ya;
                    compA[i][j][q] = (ta - acc[i][j][q]) - ya;
                    acc[i][j][q] = ta;
                }
        __syncthreads();
    }
#undef LD_STAGE
#undef EXP_STS

    rs2[tid] = rs;
    __syncthreads();
    if (tid < 128) rsum_s[tid] = rs2[tid * 2] + rs2[tid * 2 + 1];
    __syncthreads();

    int gid = lane >> 2, tid2 = lane & 3;
#pragma unroll
    for (int i = 0; i < 2; i++) {
        int rl0 = wm * 32 + i * 16 + gid;
#pragma unroll
        for (int rr = 0; rr < 2; rr++) {
            int rl = rl0 + rr * 8;
            float den = rsum_s[rl];
            size_t orow = (size_t)(b * T_LEN + rowBase + rl) * D_MODEL + h * 64;
#pragma unroll
            for (int j = 0; j < 4; j++) {
                int col = wn * 32 + j * 8 + tid2 * 2;
                float y0 = acc[i][j][rr * 2 + 0] / den;
                float y1 = acc[i][j][rr * 2 + 1] / den;
                __half u1, u2, u3, v1, v2, v3;
                split3s(y0, u1, u2, u3); split3s(y1, v1, v2, v3);
                *(uint32_t*)(g_O1 + orow + col) = packh2(u1, v1);
                *(uint32_t*)(g_O2 + orow + col) = packh2(u2, v2);
                *(uint32_t*)(g_O3 + orow + col) = packh2(u3, v3);
            }
        }
    }
}

// ---------------- fp4 quant ----------------
__global__ void k_quant(const float* __restrict__ Y, float* __restrict__ out) {
    int i = blockIdx.x * 1024 + threadIdx.x;
    float s = fmaxf(__uint_as_float(g_ymax) / 7.0f, 1e-8f);
    float q = rintf(Y[i] / s);
    out[i] = fminf(7.0f, fmaxf(-7.0f, q)) * s;
}

// ---------------- launch ----------------
extern "C" void kernel_launch(void* const* d_in, const int* in_sizes, int n_in,
                              void* d_out, int out_size) {
    const float* x  = (const float*)d_in[0];
    const float* Wq = (const float*)d_in[1];
    const float* bq = (const float*)d_in[2];
    const float* Wk = (const float*)d_in[3];
    const float* bk = (const float*)d_in[4];
    const float* Wv = (const float*)d_in[5];
    const float* bv = (const float*)d_in[6];
    const float* Wo = (const float*)d_in[7];
    const float* bo = (const float*)d_in[8];
    float* out = (float*)d_out;

    __half *tw, *x1, *x2, *x3, *q1, *q2, *q3, *kk1, *kk2, *kk3, *o1, *o2, *o3;
    float *v, *y;
    cudaGetSymbolAddress((void**)&tw, g_Tw);
    cudaGetSymbolAddress((void**)&x1, g_X1);  cudaGetSymbolAddress((void**)&x2, g_X2);
    cudaGetSymbolAddress((void**)&x3, g_X3);
    cudaGetSymbolAddress((void**)&q1, g_Q1);  cudaGetSymbolAddress((void**)&q2, g_Q2);
    cudaGetSymbolAddress((void**)&q3, g_Q3);
    cudaGetSymbolAddress((void**)&kk1, g_K1); cudaGetSymbolAddress((void**)&kk2, g_K2);
    cudaGetSymbolAddress((void**)&kk3, g_K3);
    cudaGetSymbolAddress((void**)&o1, g_O1);  cudaGetSymbolAddress((void**)&o2, g_O2);
    cudaGetSymbolAddress((void**)&o3, g_O3);
    cudaGetSymbolAddress((void**)&v, g_V);    cudaGetSymbolAddress((void**)&y, g_Y);

    cudaFuncSetAttribute(k_hproj_qkv, cudaFuncAttributeMaxDynamicSharedMemorySize, 65536);
    cudaFuncSetAttribute(k_hproj, cudaFuncAttributeMaxDynamicSharedMemorySize, 65536);
    cudaFuncSetAttribute(k_hs, cudaFuncAttributeMaxDynamicSharedMemorySize, 98304);
    cudaFuncSetAttribute(k_pvh, cudaFuncAttributeMaxDynamicSharedMemorySize, 147456);

    // 1-4) weight stats (+ folded inits) + alpha + ternarize
    k_wabs<<<dim3(1024, 4), 256>>>(Wq, Wk, Wv, Wo);
    k_wmask<<<dim3(1024, 4), 256>>>(Wq, Wk, Wv, Wo);
    k_walpha<<<4, 1024>>>();
    k_wtern<<<dim3(512, 4), 1024>>>(Wq, Wk, Wv, Wo);

    // 5) x -> scaled fp16 triple
    k_split3<<<512, 1024>>>(x);

    // 6) merged Q/K/V projections (double-buffered)
    k_hproj_qkv<<<dim3(32, 8, 3), 256, 65536>>>(x1, x2, x3, tw, bq, bk, bv, v,
                                                q1, q2, q3, kk1, kk2, kk3);

    // 7) V -> transposed scaled fp16 triple
    k_vsplitT<<<dim3(32, 16, 2), 256>>>();

    // 8) S = QK^T/8 + row max
    k_hs<<<dim3(16, 16, BATCH * N_HEADS), 256, 98304>>>();

    // 9) HMMA softmax+PV (double-buffered, exp||MMA)
    k_pvh<<<dim3(16, BATCH * N_HEADS), 256, 147456>>>();

    // 10) out projection (double-buffered, + fused absmax) -> Y
    k_hproj<<<dim3(32, 8), 256, 65536>>>(o1, o2, o3, tw + 3 * (size_t)W_ELEMS, 3, bo, y);

    // 11) fp4 quant
    k_quant<<<4096, 1024>>>(y, out);
}

// round 16
// speedup vs baseline: 1.0190x; 1.0190x over previous
#include <cuda_runtime.h>
#include <cuda_fp16.h>
#include <math.h>
#include <stdint.h>

#define D_MODEL 1024
#define T_LEN   2048
#define BATCH   2
#define N_HEADS 16
#define D_HEAD  64
#define BT      (BATCH * T_LEN)
#define W_ELEMS (D_MODEL * D_MODEL)

#define SPLIT_UP   2048.0f
#define SPLIT_UP2  4194304.0f
#define SPLIT_DN   4.8828125e-4f

// ---------------- static scratch ----------------
__device__ __half g_Tw[4][W_ELEMS];
__device__ __half g_X1[BT * D_MODEL], g_X2[BT * D_MODEL], g_X3[BT * D_MODEL];
__device__ __half g_Q1[BT * D_MODEL], g_Q2[BT * D_MODEL], g_Q3[BT * D_MODEL];
__device__ __half g_K1[BT * D_MODEL], g_K2[BT * D_MODEL], g_K3[BT * D_MODEL];
__device__ float  g_V[BT * D_MODEL];
__device__ __half g_Vt1[BT * D_MODEL], g_Vt2[BT * D_MODEL], g_Vt3[BT * D_MODEL];
__device__ __half g_O1[BT * D_MODEL], g_O2[BT * D_MODEL], g_O3[BT * D_MODEL];
__device__ float  g_Y[BT * D_MODEL];
__device__ float  g_S[(size_t)BATCH * N_HEADS * T_LEN * T_LEN];   // 512 MB
__device__ unsigned g_rmax[BATCH * N_HEADS * T_LEN];
__device__ unsigned g_ymax;
__device__ double g_red[4][1024], g_red2a[4][1024], g_red2b[4][1024];
__device__ float  g_delta[4], g_alphaf[4];

// ---------------- helpers ----------------
__device__ __forceinline__ uint32_t smem_u32(const void* p) {
    uint32_t a;
    asm("{ .reg .u64 t; cvta.to.shared.u64 t, %1; cvt.u32.u64 %0, t; }" : "=r"(a) : "l"(p));
    return a;
}
__device__ __forceinline__ void ldsm4(uint32_t (&r)[4], uint32_t addr) {
    asm volatile("ldmatrix.sync.aligned.m8n8.x4.shared.b16 {%0,%1,%2,%3}, [%4];"
                 : "=r"(r[0]), "=r"(r[1]), "=r"(r[2]), "=r"(r[3]) : "r"(addr));
}
__device__ __forceinline__ void mma16816(float (&d)[4], const uint32_t (&a)[4],
                                         uint32_t b0, uint32_t b1) {
    asm volatile("mma.sync.aligned.m16n8k16.row.col.f32.f16.f16.f32 "
                 "{%0,%1,%2,%3}, {%4,%5,%6,%7}, {%8,%9}, {%0,%1,%2,%3};"
                 : "+f"(d[0]), "+f"(d[1]), "+f"(d[2]), "+f"(d[3])
                 : "r"(a[0]), "r"(a[1]), "r"(a[2]), "r"(a[3]), "r"(b0), "r"(b1));
}
__device__ __forceinline__ unsigned fenc(float f) {
    unsigned b = __float_as_uint(f);
    return (b & 0x80000000u) ? ~b : (b | 0x80000000u);
}
__device__ __forceinline__ float fdec(unsigned u) {
    unsigned b = (u & 0x80000000u) ? (u & 0x7FFFFFFFu) : ~u;
    return __uint_as_float(b);
}
__device__ __forceinline__ void split3s(float y, __half& p1, __half& p2, __half& p3) {
    p1 = __float2half_rn(y);
    float r = y - __half2float(p1);
    p2 = __float2half_rn(r * SPLIT_UP);
    float r2 = r - __half2float(p2) * SPLIT_DN;
    p3 = __float2half_rn(r2 * SPLIT_UP2);
}
__device__ __forceinline__ uint32_t packh2(__half a, __half b) {
    __half2 h = __halves2half2(a, b);
    return *(uint32_t*)&h;
}

// ---------------- weight stats ----------------
__device__ __forceinline__ const float* pick_w(const float* W0, const float* W1,
                                               const float* W2, const float* W3, int y) {
    return y == 0 ? W0 : (y == 1 ? W1 : (y == 2 ? W2 : W3));
}

__global__ void k_wabs(const float* __restrict__ W0, const float* __restrict__ W1,
                       const float* __restrict__ W2, const float* __restrict__ W3) {
    if (blockIdx.y == 0) {
        int gi = blockIdx.x * 256 + threadIdx.x;
        if (gi < BATCH * N_HEADS * T_LEN) g_rmax[gi] = 0u;
        if (gi == 0) g_ymax = 0u;
    }
    const float* W = pick_w(W0, W1, W2, W3, blockIdx.y);
    __shared__ double sm[256];
    int base = blockIdx.x * 1024;
    double s = 0.0;
    for (int i = threadIdx.x; i < 1024; i += 256) s += (double)fabsf(W[base + i]);
    sm[threadIdx.x] = s; __syncthreads();
    for (int st = 128; st > 0; st >>= 1) {
        if (threadIdx.x < st) sm[threadIdx.x] += sm[threadIdx.x + st];
        __syncthreads();
    }
    if (threadIdx.x == 0) g_red[blockIdx.y][blockIdx.x] = sm[0];
}
__global__ void k_wmask(const float* __restrict__ W0, const float* __restrict__ W1,
                        const float* __restrict__ W2, const float* __restrict__ W3) {
    int y = blockIdx.y;
    const float* W = pick_w(W0, W1, W2, W3, y);
    __shared__ double sa[256], sb[256];
    double s = 0.0;
    for (int i = threadIdx.x; i < 1024; i += 256) s += g_red[y][i];
    sa[threadIdx.x] = s; __syncthreads();
    for (int st = 128; st > 0; st >>= 1) {
        if (threadIdx.x < st) sa[threadIdx.x] += sa[threadIdx.x + st];
        __syncthreads();
    }
    float delta = (float)(0.05 * (sa[0] / (double)W_ELEMS));
    if (blockIdx.x == 0 && threadIdx.x == 0) g_delta[y] = delta;
    __syncthreads();
    int base = blockIdx.x * 1024;
    double s1 = 0.0, s2 = 0.0;
    for (int i = threadIdx.x; i < 1024; i += 256) {
        float a = fabsf(W[base + i]);
        if (a > delta) { s1 += (double)a; s2 += 1.0; }
    }
    sa[threadIdx.x] = s1; sb[threadIdx.x] = s2; __syncthreads();
    for (int st = 128; st > 0; st >>= 1) {
        if (threadIdx.x < st) { sa[threadIdx.x] += sa[threadIdx.x + st]; sb[threadIdx.x] += sb[threadIdx.x + st]; }
        __syncthreads();
    }
    if (threadIdx.x == 0) { g_red2a[y][blockIdx.x] = sa[0]; g_red2b[y][blockIdx.x] = sb[0]; }
}
// ternarize; blockIdx.x==0 blocks additionally finalize alpha (identical reduction tree)
__global__ void k_wtern(const float* __restrict__ W0, const float* __restrict__ W1,
                        const float* __restrict__ W2, const float* __restrict__ W3) {
    int y = blockIdx.y;
    __shared__ double sa[1024], sb[1024];
    if (blockIdx.x == 0) {
        sa[threadIdx.x] = g_red2a[y][threadIdx.x];
        sb[threadIdx.x] = g_red2b[y][threadIdx.x];
        __syncthreads();
        for (int st = 512; st > 0; st >>= 1) {
            if (threadIdx.x < st) { sa[threadIdx.x] += sa[threadIdx.x + st]; sb[threadIdx.x] += sb[threadIdx.x + st]; }
            __syncthreads();
        }
        if (threadIdx.x == 0) g_alphaf[y] = (float)(sa[0] / fmax(sb[0], 1.0));
    }
    const float* W = pick_w(W0, W1, W2, W3, y);
    float delta = g_delta[y];
    int i0 = (blockIdx.x * 1024 + threadIdx.x) * 8;
    float4 wa = *(const float4*)(W + i0);
    float4 wb = *(const float4*)(W + i0 + 4);
    float wv[8] = {wa.x, wa.y, wa.z, wa.w, wb.x, wb.y, wb.z, wb.w};
    __half h[8];
#pragma unroll
    for (int q = 0; q < 8; q++) {
        float w = wv[q];
        float t = (fabsf(w) > delta) ? ((w > 0.0f) ? 1.0f : -1.0f) : 0.0f;
        h[q] = __float2half_rn(t);
    }
    *(uint4*)(g_Tw[y] + i0) = *(uint4*)&h[0];
}
__global__ void k_split3(const float* __restrict__ X) {
    int i0 = (blockIdx.x * 1024 + threadIdx.x) * 8;
    float4 xa = *(const float4*)(X + i0);
    float4 xb = *(const float4*)(X + i0 + 4);
    float xv[8] = {xa.x, xa.y, xa.z, xa.w, xb.x, xb.y, xb.z, xb.w};
    __half h1[8], h2[8], h3[8];
#pragma unroll
    for (int q = 0; q < 8; q++) split3s(xv[q], h1[q], h2[q], h3[q]);
    *(uint4*)(g_X1 + i0) = *(uint4*)&h1[0];
    *(uint4*)(g_X2 + i0) = *(uint4*)&h2[0];
    *(uint4*)(g_X3 + i0) = *(uint4*)&h3[0];
}

// ---------------- tile staging ----------------
struct TileRegs { uint4 v[4]; };
__device__ __forceinline__ void tile_ldg(TileRegs& r, const __half* __restrict__ g,
                                         int row0, int col0, int lda) {
    int tid = threadIdx.x;
#pragma unroll
    for (int i = 0; i < 4; i++) {
        int idx = tid + i * 256;
        int row = idx >> 3, c = idx & 7;
        r.v[i] = *(const uint4*)(g + (size_t)(row0 + row) * lda + col0 + c * 8);
    }
}
__device__ __forceinline__ void tile_sts(__half* s, const TileRegs& r) {
    int tid = threadIdx.x;
#pragma unroll
    for (int i = 0; i < 4; i++) {
        int idx = tid + i * 256;
        int row = idx >> 3, c = idx & 7;
        int cs = c ^ (row & 7);
        *(uint4*)((char*)s + row * 128 + cs * 16) = r.v[i];
    }
}
__device__ __forceinline__ void load_tile3(__half* s0, __half* s1, __half* s2,
                                           const __half* __restrict__ g0,
                                           const __half* __restrict__ g1,
                                           const __half* __restrict__ g2,
                                           int row0, int col0, int lda) {
    TileRegs r0, r1, r2;
    tile_ldg(r0, g0, row0, col0, lda);
    tile_ldg(r1, g1, row0, col0, lda);
    tile_ldg(r2, g2, row0, col0, lda);
    tile_sts(s0, r0);
    tile_sts(s1, r1);
    tile_sts(s2, r2);
}

// 128x128 HMMA stage
__device__ __forceinline__ void hgemm_core(uint32_t aB, uint32_t bB, int wm, int wn,
                                           int lane, float (&acc)[4][4][4]) {
#pragma unroll
    for (int kf = 0; kf < 4; kf++) {
        uint32_t a[4][4];
#pragma unroll
        for (int i = 0; i < 4; i++) {
            int row = wm * 64 + i * 16 + (lane & 15);
            int ch = (kf * 2 + (lane >> 4)) ^ (row & 7);
            ldsm4(a[i], aB + (uint32_t)(row * 8 + ch) * 16);
        }
        uint32_t b[4][2];
#pragma unroll
        for (int jp = 0; jp < 2; jp++) {
            int nrow = wn * 32 + jp * 16 + (lane & 7) + ((lane >> 4) << 3);
            int ch = (kf * 2 + ((lane >> 3) & 1)) ^ (nrow & 7);
            uint32_t t[4];
            ldsm4(t, bB + (uint32_t)(nrow * 8 + ch) * 16);
            b[jp * 2][0] = t[0]; b[jp * 2][1] = t[1];
            b[jp * 2 + 1][0] = t[2]; b[jp * 2 + 1][1] = t[3];
        }
#pragma unroll
        for (int i = 0; i < 4; i++)
#pragma unroll
            for (int j = 0; j < 4; j++)
                mma16816(acc[i][j], a[i], b[j][0], b[j][1]);
    }
}
__device__ __forceinline__ void acc_scale(float (&acc)[4][4][4], float s) {
#pragma unroll
    for (int i = 0; i < 4; i++)
#pragma unroll
        for (int j = 0; j < 4; j++)
#pragma unroll
            for (int q = 0; q < 4; q++) acc[i][j][q] *= s;
}
// 128x64 HMMA stage (PV)
__device__ __forceinline__ void hgemm64(uint32_t aB, uint32_t bB, int wm, int wn,
                                        int lane, float (&acc)[2][4][4]) {
#pragma unroll
    for (int kf = 0; kf < 4; kf++) {
        uint32_t a[2][4];
#pragma unroll
        for (int i = 0; i < 2; i++) {
            int row = wm * 32 + i * 16 + (lane & 15);
            int ch = (kf * 2 + (lane >> 4)) ^ (row & 7);
            ldsm4(a[i], aB + (uint32_t)(row * 8 + ch) * 16);
        }
        uint32_t b[4][2];
#pragma unroll
        for (int jp = 0; jp < 2; jp++) {
            int nrow = wn * 32 + jp * 16 + (lane & 7) + ((lane >> 4) << 3);
            int ch = (kf * 2 + ((lane >> 3) & 1)) ^ (nrow & 7);
            uint32_t t[4];
            ldsm4(t, bB + (uint32_t)(nrow * 8 + ch) * 16);
            b[jp * 2][0] = t[0]; b[jp * 2][1] = t[1];
            b[jp * 2 + 1][0] = t[2]; b[jp * 2 + 1][1] = t[3];
        }
#pragma unroll
        for (int i = 0; i < 2; i++)
#pragma unroll
            for (int j = 0; j < 4; j++)
                mma16816(acc[i][j], a[i], b[j][0], b[j][1]);
    }
}

// ---------------- projection body (R14 two-sync form) ----------------
__device__ __forceinline__ void hproj_body(
        const __half* __restrict__ A0, const __half* __restrict__ A1,
        const __half* __restrict__ A2, const __half* __restrict__ Bw, int widx,
        const float* __restrict__ bias, float* __restrict__ outF,
        __half* __restrict__ O1, __half* __restrict__ O2, __half* __restrict__ O3,
        int mode, int do_absmax, __half* sA, __half* sB) {
    int tid = threadIdx.x, lane = tid & 31, w = tid >> 5, wm = w >> 2, wn = w & 3;
    int m0 = blockIdx.x * 128, n0 = blockIdx.y * 128;
    float acc[4][4][4];
#pragma unroll
    for (int i = 0; i < 4; i++)
#pragma unroll
        for (int j = 0; j < 4; j++)
#pragma unroll
            for (int q = 0; q < 4; q++) acc[i][j][q] = 0.0f;
    uint32_t aB = smem_u32(sA), bB = smem_u32(sB);

    const __half* As3[3] = {A2, A1, A0};
    TileRegs ra, rb;
    tile_ldg(ra, As3[0], m0, 0, D_MODEL);
    tile_ldg(rb, Bw, n0, 0, D_MODEL);

    for (int st = 0; st < 48; st++) {
        __syncthreads();
        tile_sts(sA, ra);
        tile_sts(sB, rb);
        __syncthreads();
        if (st < 47) {
            int nst = st + 1;
            tile_ldg(ra, As3[nst >> 4], m0, (nst & 15) * 64, D_MODEL);
            tile_ldg(rb, Bw, n0, (nst & 15) * 64, D_MODEL);
        }
        hgemm_core(aB, bB, wm, wn, lane, acc);
        if (st == 15 || st == 31) acc_scale(acc, SPLIT_DN);
    }

    float alpha = g_alphaf[widx];
    int gid = lane >> 2, tid2 = lane & 3;
    float lmax = 0.0f;
#pragma unroll
    for (int i = 0; i < 4; i++) {
#pragma unroll
        for (int j = 0; j < 4; j++) {
            int row = m0 + wm * 64 + i * 16 + gid;
            int col = n0 + wn * 32 + j * 8 + tid2 * 2;
            float b0 = bias[col], b1 = bias[col + 1];
            float y00 = acc[i][j][0] * alpha + b0, y01 = acc[i][j][1] * alpha + b1;
            float y10 = acc[i][j][2] * alpha + b0, y11 = acc[i][j][3] * alpha + b1;
            if (mode == 0) {
                *(float2*)(outF + (size_t)row * D_MODEL + col) = make_float2(y00, y01);
                *(float2*)(outF + (size_t)(row + 8) * D_MODEL + col) = make_float2(y10, y11);
                if (do_absmax)
                    lmax = fmaxf(lmax, fmaxf(fmaxf(fabsf(y00), fabsf(y01)),
                                             fmaxf(fabsf(y10), fabsf(y11))));
            } else {
                __half u1, u2, u3, v1, v2, v3;
                size_t r0 = (size_t)row * D_MODEL + col;
                size_t r1 = (size_t)(row + 8) * D_MODEL + col;
                split3s(y00, u1, u2, u3); split3s(y01, v1, v2, v3);
                *(uint32_t*)(O1 + r0) = packh2(u1, v1);
                *(uint32_t*)(O2 + r0) = packh2(u2, v2);
                *(uint32_t*)(O3 + r0) = packh2(u3, v3);
                split3s(y10, u1, u2, u3); split3s(y11, v1, v2, v3);
                *(uint32_t*)(O1 + r1) = packh2(u1, v1);
                *(uint32_t*)(O2 + r1) = packh2(u2, v2);
                *(uint32_t*)(O3 + r1) = packh2(u3, v3);
            }
        }
    }
    if (mode == 0 && do_absmax) {
#pragma unroll
        for (int off = 16; off > 0; off >>= 1)
            lmax = fmaxf(lmax, __shfl_xor_sync(0xFFFFFFFF, lmax, off));
        if (lane == 0) atomicMax(&g_ymax, __float_as_uint(lmax));
    }
}

__global__ void __launch_bounds__(256)
k_hproj_qkv(const __half* __restrict__ x1, const __half* __restrict__ x2,
            const __half* __restrict__ x3, const __half* __restrict__ tw,
            const float* __restrict__ bq, const float* __restrict__ bk,
            const float* __restrict__ bv, float* __restrict__ vout,
            __half* __restrict__ q1, __half* __restrict__ q2, __half* __restrict__ q3,
            __half* __restrict__ kk1, __half* __restrict__ kk2, __half* __restrict__ kk3) {
    extern __shared__ __align__(16) __half smp[];
    int z = blockIdx.z;
    const __half* Bw = tw + (size_t)z * W_ELEMS;
    const float* bias = (z == 0) ? bq : (z == 1 ? bk : bv);
    if (z == 2)
        hproj_body(x1, x2, x3, Bw, 2, bias, vout, nullptr, nullptr, nullptr, 0, 0, smp, smp + 8192);
    else if (z == 0)
        hproj_body(x1, x2, x3, Bw, 0, bias, nullptr, q1, q2, q3, 1, 0, smp, smp + 8192);
    else
        hproj_body(x1, x2, x3, Bw, 1, bias, nullptr, kk1, kk2, kk3, 1, 0, smp, smp + 8192);
}

__global__ void __launch_bounds__(256)
k_hproj(const __half* __restrict__ A0, const __half* __restrict__ A1,
        const __half* __restrict__ A2, const __half* __restrict__ Bw, int widx,
        const float* __restrict__ bias, float* __restrict__ outF) {
    extern __shared__ __align__(16) __half smp[];
    hproj_body(A0, A1, A2, Bw, widx, bias, outF, nullptr, nullptr, nullptr, 0, 1, smp, smp + 8192);
}

// ---------------- V transpose + split ----------------
__global__ void __launch_bounds__(256)
k_vsplitT() {
    __shared__ float sT[64][65];
    int t0 = blockIdx.x * 64, d0 = blockIdx.y * 64, b = blockIdx.z;
    int tid = threadIdx.x;
    const float* V = g_V + ((size_t)b * T_LEN) * D_MODEL;
#pragma unroll
    for (int i = 0; i < 4; i++) {
        int idx4 = tid + i * 256;
        int tok = idx4 >> 4, c4 = idx4 & 15;
        float4 v = *(const float4*)(V + (size_t)(t0 + tok) * D_MODEL + d0 + c4 * 4);
        sT[tok][c4 * 4 + 0] = v.x;
        sT[tok][c4 * 4 + 1] = v.y;
        sT[tok][c4 * 4 + 2] = v.z;
        sT[tok][c4 * 4 + 3] = v.w;
    }
    __syncthreads();
    int d = tid >> 2, chunk = tid & 3;
    __half h1[16], h2[16], h3[16];
#pragma unroll
    for (int j = 0; j < 16; j++)
        split3s(sT[chunk * 16 + j][d], h1[j], h2[j], h3[j]);
    size_t base = ((size_t)b * D_MODEL + d0 + d) * T_LEN + t0 + chunk * 16;
    *(uint4*)(g_Vt1 + base) = *(uint4*)&h1[0];
    *(uint4*)(g_Vt1 + base + 8) = *(uint4*)&h1[8];
    *(uint4*)(g_Vt2 + base) = *(uint4*)&h2[0];
    *(uint4*)(g_Vt2 + base + 8) = *(uint4*)&h2[8];
    *(uint4*)(g_Vt3 + base) = *(uint4*)&h3[0];
    *(uint4*)(g_Vt3 + base + 8) = *(uint4*)&h3[8];
}

// ---------------- S = (QK^T)/8 + row max (2 CTAs/SM target) ----------------
__global__ void __launch_bounds__(256, 2)
k_hs() {
    extern __shared__ __align__(16) __half sms[];
    __half* sQ[3] = {sms, sms + 8192, sms + 16384};
    __half* sK[3] = {sms + 24576, sms + 32768, sms + 40960};

    int tid = threadIdx.x, lane = tid & 31, w = tid >> 5, wm = w >> 2, wn = w & 3;
    int z = blockIdx.z, b = z >> 4, h = z & 15;
    int arow0 = b * T_LEN + blockIdx.x * 128;
    int brow0 = b * T_LEN + blockIdx.y * 128;
    int col0 = h * 64;
    float acc[4][4][4];
#pragma unroll
    for (int i = 0; i < 4; i++)
#pragma unroll
        for (int j = 0; j < 4; j++)
#pragma unroll
            for (int q = 0; q < 4; q++) acc[i][j][q] = 0.0f;

    load_tile3(sQ[0], sQ[1], sQ[2], g_Q1, g_Q2, g_Q3, arow0, col0, D_MODEL);
    load_tile3(sK[0], sK[1], sK[2], g_K1, g_K2, g_K3, brow0, col0, D_MODEL);
    __syncthreads();

    uint32_t qB[3] = {smem_u32(sQ[0]), smem_u32(sQ[1]), smem_u32(sQ[2])};
    uint32_t kB[3] = {smem_u32(sK[0]), smem_u32(sK[1]), smem_u32(sK[2])};
    hgemm_core(qB[1], kB[1], wm, wn, lane, acc);
    hgemm_core(qB[0], kB[2], wm, wn, lane, acc);
    hgemm_core(qB[2], kB[0], wm, wn, lane, acc);
    acc_scale(acc, SPLIT_DN);
    hgemm_core(qB[0], kB[1], wm, wn, lane, acc);
    hgemm_core(qB[1], kB[0], wm, wn, lane, acc);
    acc_scale(acc, SPLIT_DN);
    hgemm_core(qB[0], kB[0], wm, wn, lane, acc);

    int gid = lane >> 2, tid2 = lane & 3;
    size_t zrow = (size_t)z * T_LEN;
#pragma unroll
    for (int i = 0; i < 4; i++) {
        int rl0 = blockIdx.x * 128 + wm * 64 + i * 16 + gid;
        float m0v = -INFINITY, m1v = -INFINITY;
#pragma unroll
        for (int j = 0; j < 4; j++) {
            int col = blockIdx.y * 128 + wn * 32 + j * 8 + tid2 * 2;
            float y00 = acc[i][j][0] * 0.125f, y01 = acc[i][j][1] * 0.125f;
            float y10 = acc[i][j][2] * 0.125f, y11 = acc[i][j][3] * 0.125f;
            *(float2*)(g_S + (zrow + rl0) * T_LEN + col) = make_float2(y00, y01);
            *(float2*)(g_S + (zrow + rl0 + 8) * T_LEN + col) = make_float2(y10, y11);
            m0v = fmaxf(m0v, fmaxf(y00, y01));
            m1v = fmaxf(m1v, fmaxf(y10, y11));
        }
        atomicMax(&g_rmax[zrow + rl0], fenc(m0v));
        atomicMax(&g_rmax[zrow + rl0 + 8], fenc(m1v));
    }
}

// ---- HMMA softmax+PV: double-buffered, exp||MMA (R12/R14) ----
__global__ void __launch_bounds__(256)
k_pvh() {
    extern __shared__ __align__(16) char smv[];
    __shared__ float m_s[128];
    __shared__ float rs2[256];
    __shared__ float rsum_s[128];

    int tid = threadIdx.x, lane = tid & 31, w = tid >> 5;
    int wm = w >> 1, wn = w & 1;
    int z = blockIdx.y, b = z >> 4, h = z & 15;
    int rowBase = blockIdx.x * 128;
    const float* Sp = g_S + ((size_t)z * T_LEN + rowBase) * T_LEN;
    size_t vbase = (size_t)b * D_MODEL + h * 64;

    if (tid < 128) m_s[tid] = fdec(g_rmax[(size_t)z * T_LEN + rowBase + tid]);
    __syncthreads();

    float acc[2][4][4], compA[2][4][4];
#pragma unroll
    for (int i = 0; i < 2; i++)
#pragma unroll
        for (int j = 0; j < 4; j++)
#pragma unroll
            for (int q = 0; q < 4; q++) { acc[i][j][q] = 0.0f; compA[i][j][q] = 0.0f; }
    float rs = 0.0f, rcomp = 0.0f;

    int prow = tid >> 1;
    int pcb = (tid & 1) * 32;
    float pm = m_s[prow];

    int vrow0 = tid >> 3, vc0 = tid & 7;
    int vrow1 = (tid + 256) >> 3, vc1 = (tid + 256) & 7;
    uint32_t voff0 = (uint32_t)vrow0 * 128 + (uint32_t)((vc0 ^ (vrow0 & 7)) * 16);
    uint32_t voff1 = (uint32_t)vrow1 * 128 + (uint32_t)((vc1 ^ (vrow1 & 7)) * 16);

    float4 sv[8];
    uint4 vv[2][3];

#define LD_STAGE(kk) do { \
    int _k0 = (kk) * 64; \
    _Pragma("unroll") \
    for (int cc = 0; cc < 4; cc++) { \
        int colb = pcb + cc * 8; \
        sv[cc * 2]     = *(const float4*)(Sp + (size_t)prow * T_LEN + _k0 + colb); \
        sv[cc * 2 + 1] = *(const float4*)(Sp + (size_t)prow * T_LEN + _k0 + colb + 4); \
    } \
    { size_t _s0 = (vbase + vrow0) * T_LEN + _k0 + vc0 * 8; \
      vv[0][0] = *(const uint4*)(g_Vt1 + _s0); \
      vv[0][1] = *(const uint4*)(g_Vt2 + _s0); \
      vv[0][2] = *(const uint4*)(g_Vt3 + _s0); } \
    { size_t _s1 = (vbase + vrow1) * T_LEN + _k0 + vc1 * 8; \
      vv[1][0] = *(const uint4*)(g_Vt1 + _s1); \
      vv[1][1] = *(const uint4*)(g_Vt2 + _s1); \
      vv[1][2] = *(const uint4*)(g_Vt3 + _s1); } \
} while (0)

#define EXP_STS(bufb) do { \
    char* _P0 = smv + (bufb) * 73728; \
    char* _P1 = _P0 + 16384; \
    char* _P2 = _P0 + 32768; \
    char* _V0 = _P0 + 49152; \
    char* _V1 = _P0 + 57344; \
    char* _V2 = _P0 + 65536; \
    float csum = 0.0f; \
    _Pragma("unroll") \
    for (int cc = 0; cc < 4; cc++) { \
        int colb = pcb + cc * 8; \
        float4 v0 = sv[cc * 2], v1 = sv[cc * 2 + 1]; \
        float e[8] = {expf(v0.x - pm), expf(v0.y - pm), expf(v0.z - pm), expf(v0.w - pm), \
                      expf(v1.x - pm), expf(v1.y - pm), expf(v1.z - pm), expf(v1.w - pm)}; \
        _Pragma("unroll") \
        for (int q = 0; q < 8; q++) csum += e[q]; \
        __half h1[8], h2[8], h3[8]; \
        _Pragma("unroll") \
        for (int q = 0; q < 8; q++) split3s(e[q], h1[q], h2[q], h3[q]); \
        int c16 = colb >> 3; \
        int cs = c16 ^ (prow & 7); \
        uint32_t off = (uint32_t)prow * 128 + cs * 16; \
        *(uint4*)(_P0 + off) = *(uint4*)&h1[0]; \
        *(uint4*)(_P1 + off) = *(uint4*)&h2[0]; \
        *(uint4*)(_P2 + off) = *(uint4*)&h3[0]; \
    } \
    { float yv = csum - rcomp; float t = rs + yv; rcomp = (t - rs) - yv; rs = t; } \
    *(uint4*)(_V0 + voff0) = vv[0][0]; \
    *(uint4*)(_V1 + voff0) = vv[0][1]; \
    *(uint4*)(_V2 + voff0) = vv[0][2]; \
    *(uint4*)(_V0 + voff1) = vv[1][0]; \
    *(uint4*)(_V1 + voff1) = vv[1][1]; \
    *(uint4*)(_V2 + voff1) = vv[1][2]; \
} while (0)

    LD_STAGE(0);
    EXP_STS(0);
    LD_STAGE(1);
    __syncthreads();

    for (int k = 0; k < 32; k++) {
        int kb = k & 1;
        uint32_t base = smem_u32(smv + kb * 73728);
        uint32_t aP0 = base, aP1 = base + 16384, aP2 = base + 32768;
        uint32_t bV0 = base + 49152, bV1 = base + 57344, bV2 = base + 65536;

        if (k < 31) {
            EXP_STS((k + 1) & 1);
            if (k < 30) LD_STAGE(k + 2);
        }

        float cacc[2][4][4];
#pragma unroll
        for (int i = 0; i < 2; i++)
#pragma unroll
            for (int j = 0; j < 4; j++)
#pragma unroll
                for (int q = 0; q < 4; q++) cacc[i][j][q] = 0.0f;
        hgemm64(aP0, bV2, wm, wn, lane, cacc);
        hgemm64(aP1, bV1, wm, wn, lane, cacc);
        hgemm64(aP2, bV0, wm, wn, lane, cacc);
#pragma unroll
        for (int i = 0; i < 2; i++)
#pragma unroll
            for (int j = 0; j < 4; j++)
#pragma unroll
                for (int q = 0; q < 4; q++) cacc[i][j][q] *= SPLIT_DN;
        hgemm64(aP0, bV1, wm, wn, lane, cacc);
        hgemm64(aP1, bV0, wm, wn, lane, cacc);
#pragma unroll
        for (int i = 0; i < 2; i++)
#pragma unroll
            for (int j = 0; j < 4; j++)
#pragma unroll
                for (int q = 0; q < 4; q++) cacc[i][j][q] *= SPLIT_DN;
        hgemm64(aP0, bV0, wm, wn, lane, cacc);
#pragma unroll
        for (int i = 0; i < 2; i++)
#pragma unroll
            for (int j = 0; j < 4; j++)
#pragma unroll
                for (int q = 0; q < 4; q++) {
                    float ya = cacc[i][j][q] - compA[i][j][q];
                    float ta = acc[i][j][q] + ya;
                    compA[i][j][q] = (ta - acc[i][j][q]) - ya;
                    acc[i][j][q] = ta;
                }
        __syncthreads();
    }
#undef LD_STAGE
#undef EXP_STS

    rs2[tid] = rs;
    __syncthreads();
    if (tid < 128) rsum_s[tid] = rs2[tid * 2] + rs2[tid * 2 + 1];
    __syncthreads();

    int gid = lane >> 2, tid2 = lane & 3;
#pragma unroll
    for (int i = 0; i < 2; i++) {
        int rl0 = wm * 32 + i * 16 + gid;
#pragma unroll
        for (int rr = 0; rr < 2; rr++) {
            int rl = rl0 + rr * 8;
            float den = rsum_s[rl];
            size_t orow = (size_t)(b * T_LEN + rowBase + rl) * D_MODEL + h * 64;
#pragma unroll
            for (int j = 0; j < 4; j++) {
                int col = wn * 32 + j * 8 + tid2 * 2;
                float y0 = acc[i][j][rr * 2 + 0] / den;
                float y1 = acc[i][j][rr * 2 + 1] / den;
                __half u1, u2, u3, v1, v2, v3;
                split3s(y0, u1, u2, u3); split3s(y1, v1, v2, v3);
                *(uint32_t*)(g_O1 + orow + col) = packh2(u1, v1);
                *(uint32_t*)(g_O2 + orow + col) = packh2(u2, v2);
                *(uint32_t*)(g_O3 + orow + col) = packh2(u3, v3);
            }
        }
    }
}

// ---------------- fp4 quant ----------------
__global__ void k_quant(const float* __restrict__ Y, float* __restrict__ out) {
    int i = blockIdx.x * 1024 + threadIdx.x;
    float s = fmaxf(__uint_as_float(g_ymax) / 7.0f, 1e-8f);
    float q = rintf(Y[i] / s);
    out[i] = fminf(7.0f, fmaxf(-7.0f, q)) * s;
}

// ---------------- launch ----------------
extern "C" void kernel_launch(void* const* d_in, const int* in_sizes, int n_in,
                              void* d_out, int out_size) {
    const float* x  = (const float*)d_in[0];
    const float* Wq = (const float*)d_in[1];
    const float* bq = (const float*)d_in[2];
    const float* Wk = (const float*)d_in[3];
    const float* bk = (const float*)d_in[4];
    const float* Wv = (const float*)d_in[5];
    const float* bv = (const float*)d_in[6];
    const float* Wo = (const float*)d_in[7];
    const float* bo = (const float*)d_in[8];
    float* out = (float*)d_out;

    __half *tw, *x1, *x2, *x3, *q1, *q2, *q3, *kk1, *kk2, *kk3, *o1, *o2, *o3;
    float *v, *y;
    cudaGetSymbolAddress((void**)&tw, g_Tw);
    cudaGetSymbolAddress((void**)&x1, g_X1);  cudaGetSymbolAddress((void**)&x2, g_X2);
    cudaGetSymbolAddress((void**)&x3, g_X3);
    cudaGetSymbolAddress((void**)&q1, g_Q1);  cudaGetSymbolAddress((void**)&q2, g_Q2);
    cudaGetSymbolAddress((void**)&q3, g_Q3);
    cudaGetSymbolAddress((void**)&kk1, g_K1); cudaGetSymbolAddress((void**)&kk2, g_K2);
    cudaGetSymbolAddress((void**)&kk3, g_K3);
    cudaGetSymbolAddress((void**)&o1, g_O1);  cudaGetSymbolAddress((void**)&o2, g_O2);
    cudaGetSymbolAddress((void**)&o3, g_O3);
    cudaGetSymbolAddress((void**)&v, g_V);    cudaGetSymbolAddress((void**)&y, g_Y);

    cudaFuncSetAttribute(k_hproj_qkv, cudaFuncAttributeMaxDynamicSharedMemorySize, 32768);
    cudaFuncSetAttribute(k_hproj, cudaFuncAttributeMaxDynamicSharedMemorySize, 32768);
    cudaFuncSetAttribute(k_hs, cudaFuncAttributeMaxDynamicSharedMemorySize, 98304);
    cudaFuncSetAttribute(k_pvh, cudaFuncAttributeMaxDynamicSharedMemorySize, 147456);

    // 1-4) weight stats (+ folded inits) + ternarize (+ folded alpha)
    k_wabs<<<dim3(1024, 4), 256>>>(Wq, Wk, Wv, Wo);
    k_wmask<<<dim3(1024, 4), 256>>>(Wq, Wk, Wv, Wo);
    k_wtern<<<dim3(512, 4), 1024>>>(Wq, Wk, Wv, Wo);

    // 5) x -> scaled fp16 triple
    k_split3<<<512, 1024>>>(x);

    // 6) merged Q/K/V projections
    k_hproj_qkv<<<dim3(32, 8, 3), 256, 32768>>>(x1, x2, x3, tw, bq, bk, bv, v,
                                                q1, q2, q3, kk1, kk2, kk3);

    // 7) V -> transposed scaled fp16 triple
    k_vsplitT<<<dim3(32, 16, 2), 256>>>();

    // 8) S = QK^T/8 + row max (2 CTAs/SM)
    k_hs<<<dim3(16, 16, BATCH * N_HEADS), 256, 98304>>>();

    // 9) HMMA softmax+PV (double-buffered, exp||MMA)
    k_pvh<<<dim3(16, BATCH * N_HEADS), 256, 147456>>>();

    // 10) out projection (+ fused absmax) -> Y
    k_hproj<<<dim3(32, 8), 256, 32768>>>(o1, o2, o3, tw + 3 * (size_t)W_ELEMS, 3, bo, y);

    // 11) fp4 quant
    k_quant<<<4096, 1024>>>(y, out);
}

// round 17
// speedup vs baseline: 1.0279x; 1.0087x over previous
#include <cuda_runtime.h>
#include <cuda_fp16.h>
#include <math.h>
#include <stdint.h>

#define D_MODEL 1024
#define T_LEN   2048
#define BATCH   2
#define N_HEADS 16
#define D_HEAD  64
#define BT      (BATCH * T_LEN)
#define W_ELEMS (D_MODEL * D_MODEL)

#define SPLIT_UP   2048.0f
#define SPLIT_UP2  4194304.0f
#define SPLIT_DN   4.8828125e-4f

// ---------------- static scratch ----------------
__device__ __half g_Tw[4][W_ELEMS];
__device__ __half g_X1[BT * D_MODEL], g_X2[BT * D_MODEL], g_X3[BT * D_MODEL];
__device__ __half g_Q1[BT * D_MODEL], g_Q2[BT * D_MODEL], g_Q3[BT * D_MODEL];
__device__ __half g_K1[BT * D_MODEL], g_K2[BT * D_MODEL], g_K3[BT * D_MODEL];
__device__ float  g_V[BT * D_MODEL];
__device__ __half g_Vt1[BT * D_MODEL], g_Vt2[BT * D_MODEL], g_Vt3[BT * D_MODEL];
__device__ __half g_O1[BT * D_MODEL], g_O2[BT * D_MODEL], g_O3[BT * D_MODEL];
__device__ float  g_Y[BT * D_MODEL];
__device__ float  g_S[(size_t)BATCH * N_HEADS * T_LEN * T_LEN];   // 512 MB
__device__ unsigned g_rmax[BATCH * N_HEADS * T_LEN];
__device__ unsigned g_ymax;
__device__ double g_red[4][1024], g_red2a[4][1024], g_red2b[4][1024];
__device__ float  g_delta[4], g_alphaf[4];

// ---------------- helpers ----------------
__device__ __forceinline__ uint32_t smem_u32(const void* p) {
    uint32_t a;
    asm("{ .reg .u64 t; cvta.to.shared.u64 t, %1; cvt.u32.u64 %0, t; }" : "=r"(a) : "l"(p));
    return a;
}
__device__ __forceinline__ void ldsm4(uint32_t (&r)[4], uint32_t addr) {
    asm volatile("ldmatrix.sync.aligned.m8n8.x4.shared.b16 {%0,%1,%2,%3}, [%4];"
                 : "=r"(r[0]), "=r"(r[1]), "=r"(r[2]), "=r"(r[3]) : "r"(addr));
}
__device__ __forceinline__ void mma16816(float (&d)[4], const uint32_t (&a)[4],
                                         uint32_t b0, uint32_t b1) {
    asm volatile("mma.sync.aligned.m16n8k16.row.col.f32.f16.f16.f32 "
                 "{%0,%1,%2,%3}, {%4,%5,%6,%7}, {%8,%9}, {%0,%1,%2,%3};"
                 : "+f"(d[0]), "+f"(d[1]), "+f"(d[2]), "+f"(d[3])
                 : "r"(a[0]), "r"(a[1]), "r"(a[2]), "r"(a[3]), "r"(b0), "r"(b1));
}
__device__ __forceinline__ unsigned fenc(float f) {
    unsigned b = __float_as_uint(f);
    return (b & 0x80000000u) ? ~b : (b | 0x80000000u);
}
__device__ __forceinline__ float fdec(unsigned u) {
    unsigned b = (u & 0x80000000u) ? (u & 0x7FFFFFFFu) : ~u;
    return __uint_as_float(b);
}
__device__ __forceinline__ void split3s(float y, __half& p1, __half& p2, __half& p3) {
    p1 = __float2half_rn(y);
    float r = y - __half2float(p1);
    p2 = __float2half_rn(r * SPLIT_UP);
    float r2 = r - __half2float(p2) * SPLIT_DN;
    p3 = __float2half_rn(r2 * SPLIT_UP2);
}
__device__ __forceinline__ uint32_t packh2(__half a, __half b) {
    __half2 h = __halves2half2(a, b);
    return *(uint32_t*)&h;
}

// ---------------- weight stats ----------------
__device__ __forceinline__ const float* pick_w(const float* W0, const float* W1,
                                               const float* W2, const float* W3, int y) {
    return y == 0 ? W0 : (y == 1 ? W1 : (y == 2 ? W2 : W3));
}

__global__ void k_wabs(const float* __restrict__ W0, const float* __restrict__ W1,
                       const float* __restrict__ W2, const float* __restrict__ W3) {
    if (blockIdx.y == 0) {
        int gi = blockIdx.x * 256 + threadIdx.x;
        if (gi < BATCH * N_HEADS * T_LEN) g_rmax[gi] = 0u;
        if (gi == 0) g_ymax = 0u;
    }
    const float* W = pick_w(W0, W1, W2, W3, blockIdx.y);
    __shared__ double sm[256];
    int base = blockIdx.x * 1024;
    double s = 0.0;
    for (int i = threadIdx.x; i < 1024; i += 256) s += (double)fabsf(W[base + i]);
    sm[threadIdx.x] = s; __syncthreads();
    for (int st = 128; st > 0; st >>= 1) {
        if (threadIdx.x < st) sm[threadIdx.x] += sm[threadIdx.x + st];
        __syncthreads();
    }
    if (threadIdx.x == 0) g_red[blockIdx.y][blockIdx.x] = sm[0];
}
__global__ void k_wmask(const float* __restrict__ W0, const float* __restrict__ W1,
                        const float* __restrict__ W2, const float* __restrict__ W3) {
    int y = blockIdx.y;
    const float* W = pick_w(W0, W1, W2, W3, y);
    __shared__ double sa[256], sb[256];
    double s = 0.0;
    for (int i = threadIdx.x; i < 1024; i += 256) s += g_red[y][i];
    sa[threadIdx.x] = s; __syncthreads();
    for (int st = 128; st > 0; st >>= 1) {
        if (threadIdx.x < st) sa[threadIdx.x] += sa[threadIdx.x + st];
        __syncthreads();
    }
    float delta = (float)(0.05 * (sa[0] / (double)W_ELEMS));
    if (blockIdx.x == 0 && threadIdx.x == 0) g_delta[y] = delta;
    __syncthreads();
    int base = blockIdx.x * 1024;
    double s1 = 0.0, s2 = 0.0;
    for (int i = threadIdx.x; i < 1024; i += 256) {
        float a = fabsf(W[base + i]);
        if (a > delta) { s1 += (double)a; s2 += 1.0; }
    }
    sa[threadIdx.x] = s1; sb[threadIdx.x] = s2; __syncthreads();
    for (int st = 128; st > 0; st >>= 1) {
        if (threadIdx.x < st) { sa[threadIdx.x] += sa[threadIdx.x + st]; sb[threadIdx.x] += sb[threadIdx.x + st]; }
        __syncthreads();
    }
    if (threadIdx.x == 0) { g_red2a[y][blockIdx.x] = sa[0]; g_red2b[y][blockIdx.x] = sb[0]; }
}
// ternarize; blockIdx.x==0 blocks additionally finalize alpha (identical reduction tree)
__global__ void k_wtern(const float* __restrict__ W0, const float* __restrict__ W1,
                        const float* __restrict__ W2, const float* __restrict__ W3) {
    int y = blockIdx.y;
    __shared__ double sa[1024], sb[1024];
    if (blockIdx.x == 0) {
        sa[threadIdx.x] = g_red2a[y][threadIdx.x];
        sb[threadIdx.x] = g_red2b[y][threadIdx.x];
        __syncthreads();
        for (int st = 512; st > 0; st >>= 1) {
            if (threadIdx.x < st) { sa[threadIdx.x] += sa[threadIdx.x + st]; sb[threadIdx.x] += sb[threadIdx.x + st]; }
            __syncthreads();
        }
        if (threadIdx.x == 0) g_alphaf[y] = (float)(sa[0] / fmax(sb[0], 1.0));
    }
    const float* W = pick_w(W0, W1, W2, W3, y);
    float delta = g_delta[y];
    int i0 = (blockIdx.x * 1024 + threadIdx.x) * 8;
    float4 wa = *(const float4*)(W + i0);
    float4 wb = *(const float4*)(W + i0 + 4);
    float wv[8] = {wa.x, wa.y, wa.z, wa.w, wb.x, wb.y, wb.z, wb.w};
    __half h[8];
#pragma unroll
    for (int q = 0; q < 8; q++) {
        float w = wv[q];
        float t = (fabsf(w) > delta) ? ((w > 0.0f) ? 1.0f : -1.0f) : 0.0f;
        h[q] = __float2half_rn(t);
    }
    *(uint4*)(g_Tw[y] + i0) = *(uint4*)&h[0];
}
__global__ void k_split3(const float* __restrict__ X) {
    int i0 = (blockIdx.x * 1024 + threadIdx.x) * 8;
    float4 xa = *(const float4*)(X + i0);
    float4 xb = *(const float4*)(X + i0 + 4);
    float xv[8] = {xa.x, xa.y, xa.z, xa.w, xb.x, xb.y, xb.z, xb.w};
    __half h1[8], h2[8], h3[8];
#pragma unroll
    for (int q = 0; q < 8; q++) split3s(xv[q], h1[q], h2[q], h3[q]);
    *(uint4*)(g_X1 + i0) = *(uint4*)&h1[0];
    *(uint4*)(g_X2 + i0) = *(uint4*)&h2[0];
    *(uint4*)(g_X3 + i0) = *(uint4*)&h3[0];
}

// ---------------- tile staging ----------------
struct TileRegs { uint4 v[4]; };
__device__ __forceinline__ void tile_ldg(TileRegs& r, const __half* __restrict__ g,
                                         int row0, int col0, int lda) {
    int tid = threadIdx.x;
#pragma unroll
    for (int i = 0; i < 4; i++) {
        int idx = tid + i * 256;
        int row = idx >> 3, c = idx & 7;
        r.v[i] = *(const uint4*)(g + (size_t)(row0 + row) * lda + col0 + c * 8);
    }
}
__device__ __forceinline__ void tile_sts(__half* s, const TileRegs& r) {
    int tid = threadIdx.x;
#pragma unroll
    for (int i = 0; i < 4; i++) {
        int idx = tid + i * 256;
        int row = idx >> 3, c = idx & 7;
        int cs = c ^ (row & 7);
        *(uint4*)((char*)s + row * 128 + cs * 16) = r.v[i];
    }
}
__device__ __forceinline__ void load_tile3(__half* s0, __half* s1, __half* s2,
                                           const __half* __restrict__ g0,
                                           const __half* __restrict__ g1,
                                           const __half* __restrict__ g2,
                                           int row0, int col0, int lda) {
    TileRegs r0, r1, r2;
    tile_ldg(r0, g0, row0, col0, lda);
    tile_ldg(r1, g1, row0, col0, lda);
    tile_ldg(r2, g2, row0, col0, lda);
    tile_sts(s0, r0);
    tile_sts(s1, r1);
    tile_sts(s2, r2);
}

// 128x128 HMMA stage
__device__ __forceinline__ void hgemm_core(uint32_t aB, uint32_t bB, int wm, int wn,
                                           int lane, float (&acc)[4][4][4]) {
#pragma unroll
    for (int kf = 0; kf < 4; kf++) {
        uint32_t a[4][4];
#pragma unroll
        for (int i = 0; i < 4; i++) {
            int row = wm * 64 + i * 16 + (lane & 15);
            int ch = (kf * 2 + (lane >> 4)) ^ (row & 7);
            ldsm4(a[i], aB + (uint32_t)(row * 8 + ch) * 16);
        }
        uint32_t b[4][2];
#pragma unroll
        for (int jp = 0; jp < 2; jp++) {
            int nrow = wn * 32 + jp * 16 + (lane & 7) + ((lane >> 4) << 3);
            int ch = (kf * 2 + ((lane >> 3) & 1)) ^ (nrow & 7);
            uint32_t t[4];
            ldsm4(t, bB + (uint32_t)(nrow * 8 + ch) * 16);
            b[jp * 2][0] = t[0]; b[jp * 2][1] = t[1];
            b[jp * 2 + 1][0] = t[2]; b[jp * 2 + 1][1] = t[3];
        }
#pragma unroll
        for (int i = 0; i < 4; i++)
#pragma unroll
            for (int j = 0; j < 4; j++)
                mma16816(acc[i][j], a[i], b[j][0], b[j][1]);
    }
}
__device__ __forceinline__ void acc_scale(float (&acc)[4][4][4], float s) {
#pragma unroll
    for (int i = 0; i < 4; i++)
#pragma unroll
        for (int j = 0; j < 4; j++)
#pragma unroll
            for (int q = 0; q < 4; q++) acc[i][j][q] *= s;
}
// 128x64 HMMA stage (PV)
__device__ __forceinline__ void hgemm64(uint32_t aB, uint32_t bB, int wm, int wn,
                                        int lane, float (&acc)[2][4][4]) {
#pragma unroll
    for (int kf = 0; kf < 4; kf++) {
        uint32_t a[2][4];
#pragma unroll
        for (int i = 0; i < 2; i++) {
            int row = wm * 32 + i * 16 + (lane & 15);
            int ch = (kf * 2 + (lane >> 4)) ^ (row & 7);
            ldsm4(a[i], aB + (uint32_t)(row * 8 + ch) * 16);
        }
        uint32_t b[4][2];
#pragma unroll
        for (int jp = 0; jp < 2; jp++) {
            int nrow = wn * 32 + jp * 16 + (lane & 7) + ((lane >> 4) << 3);
            int ch = (kf * 2 + ((lane >> 3) & 1)) ^ (nrow & 7);
            uint32_t t[4];
            ldsm4(t, bB + (uint32_t)(nrow * 8 + ch) * 16);
            b[jp * 2][0] = t[0]; b[jp * 2][1] = t[1];
            b[jp * 2 + 1][0] = t[2]; b[jp * 2 + 1][1] = t[3];
        }
#pragma unroll
        for (int i = 0; i < 2; i++)
#pragma unroll
            for (int j = 0; j < 4; j++)
                mma16816(acc[i][j], a[i], b[j][0], b[j][1]);
    }
}

// ---------------- projection body: no reg-prefetch; 2 CTAs/SM occupancy ----------------
__device__ __forceinline__ void hproj_body(
        const __half* __restrict__ A0, const __half* __restrict__ A1,
        const __half* __restrict__ A2, const __half* __restrict__ Bw, int widx,
        const float* __restrict__ bias, float* __restrict__ outF,
        __half* __restrict__ O1, __half* __restrict__ O2, __half* __restrict__ O3,
        int mode, int do_absmax, __half* sA, __half* sB) {
    int tid = threadIdx.x, lane = tid & 31, w = tid >> 5, wm = w >> 2, wn = w & 3;
    int m0 = blockIdx.x * 128, n0 = blockIdx.y * 128;
    float acc[4][4][4];
#pragma unroll
    for (int i = 0; i < 4; i++)
#pragma unroll
        for (int j = 0; j < 4; j++)
#pragma unroll
            for (int q = 0; q < 4; q++) acc[i][j][q] = 0.0f;
    uint32_t aB = smem_u32(sA), bB = smem_u32(sB);

    const __half* As3[3] = {A2, A1, A0};

    for (int st = 0; st < 48; st++) {
        __syncthreads();
        {
            TileRegs ra, rb;                 // transient: not live across MMA
            tile_ldg(ra, As3[st >> 4], m0, (st & 15) * 64, D_MODEL);
            tile_ldg(rb, Bw, n0, (st & 15) * 64, D_MODEL);
            tile_sts(sA, ra);
            tile_sts(sB, rb);
        }
        __syncthreads();
        hgemm_core(aB, bB, wm, wn, lane, acc);
        if (st == 15 || st == 31) acc_scale(acc, SPLIT_DN);
    }

    float alpha = g_alphaf[widx];
    int gid = lane >> 2, tid2 = lane & 3;
    float lmax = 0.0f;
#pragma unroll
    for (int i = 0; i < 4; i++) {
#pragma unroll
        for (int j = 0; j < 4; j++) {
            int row = m0 + wm * 64 + i * 16 + gid;
            int col = n0 + wn * 32 + j * 8 + tid2 * 2;
            float b0 = bias[col], b1 = bias[col + 1];
            float y00 = acc[i][j][0] * alpha + b0, y01 = acc[i][j][1] * alpha + b1;
            float y10 = acc[i][j][2] * alpha + b0, y11 = acc[i][j][3] * alpha + b1;
            if (mode == 0) {
                *(float2*)(outF + (size_t)row * D_MODEL + col) = make_float2(y00, y01);
                *(float2*)(outF + (size_t)(row + 8) * D_MODEL + col) = make_float2(y10, y11);
                if (do_absmax)
                    lmax = fmaxf(lmax, fmaxf(fmaxf(fabsf(y00), fabsf(y01)),
                                             fmaxf(fabsf(y10), fabsf(y11))));
            } else {
                __half u1, u2, u3, v1, v2, v3;
                size_t r0 = (size_t)row * D_MODEL + col;
                size_t r1 = (size_t)(row + 8) * D_MODEL + col;
                split3s(y00, u1, u2, u3); split3s(y01, v1, v2, v3);
                *(uint32_t*)(O1 + r0) = packh2(u1, v1);
                *(uint32_t*)(O2 + r0) = packh2(u2, v2);
                *(uint32_t*)(O3 + r0) = packh2(u3, v3);
                split3s(y10, u1, u2, u3); split3s(y11, v1, v2, v3);
                *(uint32_t*)(O1 + r1) = packh2(u1, v1);
                *(uint32_t*)(O2 + r1) = packh2(u2, v2);
                *(uint32_t*)(O3 + r1) = packh2(u3, v3);
            }
        }
    }
    if (mode == 0 && do_absmax) {
#pragma unroll
        for (int off = 16; off > 0; off >>= 1)
            lmax = fmaxf(lmax, __shfl_xor_sync(0xFFFFFFFF, lmax, off));
        if (lane == 0) atomicMax(&g_ymax, __float_as_uint(lmax));
    }
}

__global__ void __launch_bounds__(256, 2)
k_hproj_qkv(const __half* __restrict__ x1, const __half* __restrict__ x2,
            const __half* __restrict__ x3, const __half* __restrict__ tw,
            const float* __restrict__ bq, const float* __restrict__ bk,
            const float* __restrict__ bv, float* __restrict__ vout,
            __half* __restrict__ q1, __half* __restrict__ q2, __half* __restrict__ q3,
            __half* __restrict__ kk1, __half* __restrict__ kk2, __half* __restrict__ kk3) {
    extern __shared__ __align__(16) __half smp[];
    int z = blockIdx.z;
    const __half* Bw = tw + (size_t)z * W_ELEMS;
    const float* bias = (z == 0) ? bq : (z == 1 ? bk : bv);
    if (z == 2)
        hproj_body(x1, x2, x3, Bw, 2, bias, vout, nullptr, nullptr, nullptr, 0, 0, smp, smp + 8192);
    else if (z == 0)
        hproj_body(x1, x2, x3, Bw, 0, bias, nullptr, q1, q2, q3, 1, 0, smp, smp + 8192);
    else
        hproj_body(x1, x2, x3, Bw, 1, bias, nullptr, kk1, kk2, kk3, 1, 0, smp, smp + 8192);
}

__global__ void __launch_bounds__(256, 2)
k_hproj(const __half* __restrict__ A0, const __half* __restrict__ A1,
        const __half* __restrict__ A2, const __half* __restrict__ Bw, int widx,
        const float* __restrict__ bias, float* __restrict__ outF) {
    extern __shared__ __align__(16) __half smp[];
    hproj_body(A0, A1, A2, Bw, widx, bias, outF, nullptr, nullptr, nullptr, 0, 1, smp, smp + 8192);
}

// ---------------- V transpose + split ----------------
__global__ void __launch_bounds__(256)
k_vsplitT() {
    __shared__ float sT[64][65];
    int t0 = blockIdx.x * 64, d0 = blockIdx.y * 64, b = blockIdx.z;
    int tid = threadIdx.x;
    const float* V = g_V + ((size_t)b * T_LEN) * D_MODEL;
#pragma unroll
    for (int i = 0; i < 4; i++) {
        int idx4 = tid + i * 256;
        int tok = idx4 >> 4, c4 = idx4 & 15;
        float4 v = *(const float4*)(V + (size_t)(t0 + tok) * D_MODEL + d0 + c4 * 4);
        sT[tok][c4 * 4 + 0] = v.x;
        sT[tok][c4 * 4 + 1] = v.y;
        sT[tok][c4 * 4 + 2] = v.z;
        sT[tok][c4 * 4 + 3] = v.w;
    }
    __syncthreads();
    int d = tid >> 2, chunk = tid & 3;
    __half h1[16], h2[16], h3[16];
#pragma unroll
    for (int j = 0; j < 16; j++)
        split3s(sT[chunk * 16 + j][d], h1[j], h2[j], h3[j]);
    size_t base = ((size_t)b * D_MODEL + d0 + d) * T_LEN + t0 + chunk * 16;
    *(uint4*)(g_Vt1 + base) = *(uint4*)&h1[0];
    *(uint4*)(g_Vt1 + base + 8) = *(uint4*)&h1[8];
    *(uint4*)(g_Vt2 + base) = *(uint4*)&h2[0];
    *(uint4*)(g_Vt2 + base + 8) = *(uint4*)&h2[8];
    *(uint4*)(g_Vt3 + base) = *(uint4*)&h3[0];
    *(uint4*)(g_Vt3 + base + 8) = *(uint4*)&h3[8];
}

// ---------------- S = (QK^T)/8 + row max ----------------
__global__ void __launch_bounds__(256, 2)
k_hs() {
    extern __shared__ __align__(16) __half sms[];
    __half* sQ[3] = {sms, sms + 8192, sms + 16384};
    __half* sK[3] = {sms + 24576, sms + 32768, sms + 40960};

    int tid = threadIdx.x, lane = tid & 31, w = tid >> 5, wm = w >> 2, wn = w & 3;
    int z = blockIdx.z, b = z >> 4, h = z & 15;
    int arow0 = b * T_LEN + blockIdx.x * 128;
    int brow0 = b * T_LEN + blockIdx.y * 128;
    int col0 = h * 64;
    float acc[4][4][4];
#pragma unroll
    for (int i = 0; i < 4; i++)
#pragma unroll
        for (int j = 0; j < 4; j++)
#pragma unroll
            for (int q = 0; q < 4; q++) acc[i][j][q] = 0.0f;

    load_tile3(sQ[0], sQ[1], sQ[2], g_Q1, g_Q2, g_Q3, arow0, col0, D_MODEL);
    load_tile3(sK[0], sK[1], sK[2], g_K1, g_K2, g_K3, brow0, col0, D_MODEL);
    __syncthreads();

    uint32_t qB[3] = {smem_u32(sQ[0]), smem_u32(sQ[1]), smem_u32(sQ[2])};
    uint32_t kB[3] = {smem_u32(sK[0]), smem_u32(sK[1]), smem_u32(sK[2])};
    hgemm_core(qB[1], kB[1], wm, wn, lane, acc);
    hgemm_core(qB[0], kB[2], wm, wn, lane, acc);
    hgemm_core(qB[2], kB[0], wm, wn, lane, acc);
    acc_scale(acc, SPLIT_DN);
    hgemm_core(qB[0], kB[1], wm, wn, lane, acc);
    hgemm_core(qB[1], kB[0], wm, wn, lane, acc);
    acc_scale(acc, SPLIT_DN);
    hgemm_core(qB[0], kB[0], wm, wn, lane, acc);

    int gid = lane >> 2, tid2 = lane & 3;
    size_t zrow = (size_t)z * T_LEN;
#pragma unroll
    for (int i = 0; i < 4; i++) {
        int rl0 = blockIdx.x * 128 + wm * 64 + i * 16 + gid;
        float m0v = -INFINITY, m1v = -INFINITY;
#pragma unroll
        for (int j = 0; j < 4; j++) {
            int col = blockIdx.y * 128 + wn * 32 + j * 8 + tid2 * 2;
            float y00 = acc[i][j][0] * 0.125f, y01 = acc[i][j][1] * 0.125f;
            float y10 = acc[i][j][2] * 0.125f, y11 = acc[i][j][3] * 0.125f;
            *(float2*)(g_S + (zrow + rl0) * T_LEN + col) = make_float2(y00, y01);
            *(float2*)(g_S + (zrow + rl0 + 8) * T_LEN + col) = make_float2(y10, y11);
            m0v = fmaxf(m0v, fmaxf(y00, y01));
            m1v = fmaxf(m1v, fmaxf(y10, y11));
        }
        atomicMax(&g_rmax[zrow + rl0], fenc(m0v));
        atomicMax(&g_rmax[zrow + rl0 + 8], fenc(m1v));
    }
}

// ---- HMMA softmax+PV: double-buffered, exp||MMA ----
__global__ void __launch_bounds__(256)
k_pvh() {
    extern __shared__ __align__(16) char smv[];
    __shared__ float m_s[128];
    __shared__ float rs2[256];
    __shared__ float rsum_s[128];

    int tid = threadIdx.x, lane = tid & 31, w = tid >> 5;
    int wm = w >> 1, wn = w & 1;
    int z = blockIdx.y, b = z >> 4, h = z & 15;
    int rowBase = blockIdx.x * 128;
    const float* Sp = g_S + ((size_t)z * T_LEN + rowBase) * T_LEN;
    size_t vbase = (size_t)b * D_MODEL + h * 64;

    if (tid < 128) m_s[tid] = fdec(g_rmax[(size_t)z * T_LEN + rowBase + tid]);
    __syncthreads();

    float acc[2][4][4], compA[2][4][4];
#pragma unroll
    for (int i = 0; i < 2; i++)
#pragma unroll
        for (int j = 0; j < 4; j++)
#pragma unroll
            for (int q = 0; q < 4; q++) { acc[i][j][q] = 0.0f; compA[i][j][q] = 0.0f; }
    float rs = 0.0f, rcomp = 0.0f;

    int prow = tid >> 1;
    int pcb = (tid & 1) * 32;
    float pm = m_s[prow];

    int vrow0 = tid >> 3, vc0 = tid & 7;
    int vrow1 = (tid + 256) >> 3, vc1 = (tid + 256) & 7;
    uint32_t voff0 = (uint32_t)vrow0 * 128 + (uint32_t)((vc0 ^ (vrow0 & 7)) * 16);
    uint32_t voff1 = (uint32_t)vrow1 * 128 + (uint32_t)((vc1 ^ (vrow1 & 7)) * 16);

    float4 sv[8];
    uint4 vv[2][3];

#define LD_STAGE(kk) do { \
    int _k0 = (kk) * 64; \
    _Pragma("unroll") \
    for (int cc = 0; cc < 4; cc++) { \
        int colb = pcb + cc * 8; \
        sv[cc * 2]     = *(const float4*)(Sp + (size_t)prow * T_LEN + _k0 + colb); \
        sv[cc * 2 + 1] = *(const float4*)(Sp + (size_t)prow * T_LEN + _k0 + colb + 4); \
    } \
    { size_t _s0 = (vbase + vrow0) * T_LEN + _k0 + vc0 * 8; \
      vv[0][0] = *(const uint4*)(g_Vt1 + _s0); \
      vv[0][1] = *(const uint4*)(g_Vt2 + _s0); \
      vv[0][2] = *(const uint4*)(g_Vt3 + _s0); } \
    { size_t _s1 = (vbase + vrow1) * T_LEN + _k0 + vc1 * 8; \
      vv[1][0] = *(const uint4*)(g_Vt1 + _s1); \
      vv[1][1] = *(const uint4*)(g_Vt2 + _s1); \
      vv[1][2] = *(const uint4*)(g_Vt3 + _s1); } \
} while (0)

#define EXP_STS(bufb) do { \
    char* _P0 = smv + (bufb) * 73728; \
    char* _P1 = _P0 + 16384; \
    char* _P2 = _P0 + 32768; \
    char* _V0 = _P0 + 49152; \
    char* _V1 = _P0 + 57344; \
    char* _V2 = _P0 + 65536; \
    float csum = 0.0f; \
    _Pragma("unroll") \
    for (int cc = 0; cc < 4; cc++) { \
        int colb = pcb + cc * 8; \
        float4 v0 = sv[cc * 2], v1 = sv[cc * 2 + 1]; \
        float e[8] = {expf(v0.x - pm), expf(v0.y - pm), expf(v0.z - pm), expf(v0.w - pm), \
                      expf(v1.x - pm), expf(v1.y - pm), expf(v1.z - pm), expf(v1.w - pm)}; \
        _Pragma("unroll") \
        for (int q = 0; q < 8; q++) csum += e[q]; \
        __half h1[8], h2[8], h3[8]; \
        _Pragma("unroll") \
        for (int q = 0; q < 8; q++) split3s(e[q], h1[q], h2[q], h3[q]); \
        int c16 = colb >> 3; \
        int cs = c16 ^ (prow & 7); \
        uint32_t off = (uint32_t)prow * 128 + cs * 16; \
        *(uint4*)(_P0 + off) = *(uint4*)&h1[0]; \
        *(uint4*)(_P1 + off) = *(uint4*)&h2[0]; \
        *(uint4*)(_P2 + off) = *(uint4*)&h3[0]; \
    } \
    { float yv = csum - rcomp; float t = rs + yv; rcomp = (t - rs) - yv; rs = t; } \
    *(uint4*)(_V0 + voff0) = vv[0][0]; \
    *(uint4*)(_V1 + voff0) = vv[0][1]; \
    *(uint4*)(_V2 + voff0) = vv[0][2]; \
    *(uint4*)(_V0 + voff1) = vv[1][0]; \
    *(uint4*)(_V1 + voff1) = vv[1][1]; \
    *(uint4*)(_V2 + voff1) = vv[1][2]; \
} while (0)

    LD_STAGE(0);
    EXP_STS(0);
    LD_STAGE(1);
    __syncthreads();

    for (int k = 0; k < 32; k++) {
        int kb = k & 1;
        uint32_t base = smem_u32(smv + kb * 73728);
        uint32_t aP0 = base, aP1 = base + 16384, aP2 = base + 32768;
        uint32_t bV0 = base + 49152, bV1 = base + 57344, bV2 = base + 65536;

        if (k < 31) {
            EXP_STS((k + 1) & 1);
            if (k < 30) LD_STAGE(k + 2);
        }

        float cacc[2][4][4];
#pragma unroll
        for (int i = 0; i < 2; i++)
#pragma unroll
            for (int j = 0; j < 4; j++)
#pragma unroll
                for (int q = 0; q < 4; q++) cacc[i][j][q] = 0.0f;
        hgemm64(aP0, bV2, wm, wn, lane, cacc);
        hgemm64(aP1, bV1, wm, wn, lane, cacc);
        hgemm64(aP2, bV0, wm, wn, lane, cacc);
#pragma unroll
        for (int i = 0; i < 2; i++)
#pragma unroll
            for (int j = 0; j < 4; j++)
#pragma unroll
                for (int q = 0; q < 4; q++) cacc[i][j][q] *= SPLIT_DN;
        hgemm64(aP0, bV1, wm, wn, lane, cacc);
        hgemm64(aP1, bV0, wm, wn, lane, cacc);
#pragma unroll
        for (int i = 0; i < 2; i++)
#pragma unroll
            for (int j = 0; j < 4; j++)
#pragma unroll
                for (int q = 0; q < 4; q++) cacc[i][j][q] *= SPLIT_DN;
        hgemm64(aP0, bV0, wm, wn, lane, cacc);
#pragma unroll
        for (int i = 0; i < 2; i++)
#pragma unroll
            for (int j = 0; j < 4; j++)
#pragma unroll
                for (int q = 0; q < 4; q++) {
                    float ya = cacc[i][j][q] - compA[i][j][q];
                    float ta = acc[i][j][q] + ya;
                    compA[i][j][q] = (ta - acc[i][j][q]) - ya;
                    acc[i][j][q] = ta;
                }
        __syncthreads();
    }
#undef LD_STAGE
#undef EXP_STS

    rs2[tid] = rs;
    __syncthreads();
    if (tid < 128) rsum_s[tid] = rs2[tid * 2] + rs2[tid * 2 + 1];
    __syncthreads();

    int gid = lane >> 2, tid2 = lane & 3;
#pragma unroll
    for (int i = 0; i < 2; i++) {
        int rl0 = wm * 32 + i * 16 + gid;
#pragma unroll
        for (int rr = 0; rr < 2; rr++) {
            int rl = rl0 + rr * 8;
            float den = rsum_s[rl];
            size_t orow = (size_t)(b * T_LEN + rowBase + rl) * D_MODEL + h * 64;
#pragma unroll
            for (int j = 0; j < 4; j++) {
                int col = wn * 32 + j * 8 + tid2 * 2;
                float y0 = acc[i][j][rr * 2 + 0] / den;
                float y1 = acc[i][j][rr * 2 + 1] / den;
                __half u1, u2, u3, v1, v2, v3;
                split3s(y0, u1, u2, u3); split3s(y1, v1, v2, v3);
                *(uint32_t*)(g_O1 + orow + col) = packh2(u1, v1);
                *(uint32_t*)(g_O2 + orow + col) = packh2(u2, v2);
                *(uint32_t*)(g_O3 + orow + col) = packh2(u3, v3);
            }
        }
    }
}

// ---------------- fp4 quant ----------------
__global__ void k_quant(const float* __restrict__ Y, float* __restrict__ out) {
    int i = blockIdx.x * 1024 + threadIdx.x;
    float s = fmaxf(__uint_as_float(g_ymax) / 7.0f, 1e-8f);
    float q = rintf(Y[i] / s);
    out[i] = fminf(7.0f, fmaxf(-7.0f, q)) * s;
}

// ---------------- launch ----------------
extern "C" void kernel_launch(void* const* d_in, const int* in_sizes, int n_in,
                              void* d_out, int out_size) {
    const float* x  = (const float*)d_in[0];
    const float* Wq = (const float*)d_in[1];
    const float* bq = (const float*)d_in[2];
    const float* Wk = (const float*)d_in[3];
    const float* bk = (const float*)d_in[4];
    const float* Wv = (const float*)d_in[5];
    const float* bv = (const float*)d_in[6];
    const float* Wo = (const float*)d_in[7];
    const float* bo = (const float*)d_in[8];
    float* out = (float*)d_out;

    __half *tw, *x1, *x2, *x3, *q1, *q2, *q3, *kk1, *kk2, *kk3, *o1, *o2, *o3;
    float *v, *y;
    cudaGetSymbolAddress((void**)&tw, g_Tw);
    cudaGetSymbolAddress((void**)&x1, g_X1);  cudaGetSymbolAddress((void**)&x2, g_X2);
    cudaGetSymbolAddress((void**)&x3, g_X3);
    cudaGetSymbolAddress((void**)&q1, g_Q1);  cudaGetSymbolAddress((void**)&q2, g_Q2);
    cudaGetSymbolAddress((void**)&q3, g_Q3);
    cudaGetSymbolAddress((void**)&kk1, g_K1); cudaGetSymbolAddress((void**)&kk2, g_K2);
    cudaGetSymbolAddress((void**)&kk3, g_K3);
    cudaGetSymbolAddress((void**)&o1, g_O1);  cudaGetSymbolAddress((void**)&o2, g_O2);
    cudaGetSymbolAddress((void**)&o3, g_O3);
    cudaGetSymbolAddress((void**)&v, g_V);    cudaGetSymbolAddress((void**)&y, g_Y);

    cudaFuncSetAttribute(k_hproj_qkv, cudaFuncAttributeMaxDynamicSharedMemorySize, 32768);
    cudaFuncSetAttribute(k_hproj, cudaFuncAttributeMaxDynamicSharedMemorySize, 32768);
    cudaFuncSetAttribute(k_hs, cudaFuncAttributeMaxDynamicSharedMemorySize, 98304);
    cudaFuncSetAttribute(k_pvh, cudaFuncAttributeMaxDynamicSharedMemorySize, 147456);

    // 1-3) weight stats (+ folded inits) + ternarize (+ folded alpha)
    k_wabs<<<dim3(1024, 4), 256>>>(Wq, Wk, Wv, Wo);
    k_wmask<<<dim3(1024, 4), 256>>>(Wq, Wk, Wv, Wo);
    k_wtern<<<dim3(512, 4), 1024>>>(Wq, Wk, Wv, Wo);

    // 4) x -> scaled fp16 triple
    k_split3<<<512, 1024>>>(x);

    // 5) merged Q/K/V projections (occupancy-2, no reg prefetch)
    k_hproj_qkv<<<dim3(32, 8, 3), 256, 32768>>>(x1, x2, x3, tw, bq, bk, bv, v,
                                                q1, q2, q3, kk1, kk2, kk3);

    // 6) V -> transposed scaled fp16 triple
    k_vsplitT<<<dim3(32, 16, 2), 256>>>();

    // 7) S = QK^T/8 + row max
    k_hs<<<dim3(16, 16, BATCH * N_HEADS), 256, 98304>>>();

    // 8) HMMA softmax+PV (double-buffered, exp||MMA)
    k_pvh<<<dim3(16, BATCH * N_HEADS), 256, 147456>>>();

    // 9) out projection (occupancy-2, + fused absmax) -> Y
    k_hproj<<<dim3(32, 8), 256, 32768>>>(o1, o2, o3, tw + 3 * (size_t)W_ELEMS, 3, bo, y);

    // 10) fp4 quant
    k_quant<<<4096, 1024>>>(y, out);
}